// round 11
// baseline (speedup 1.0000x reference)
#include <cuda_runtime.h>
#include <cuda_fp16.h>
#include <cuda_bf16.h>
#include <math.h>
#include <stdint.h>

#define BATCH 2
#define SEQ   2048
#define DIM   4096
#define NH    32
#define NKV   8
#define HD    128
#define MROWS 4096   // BATCH*SEQ
#define KVDIM 1024   // NKV*HD
#define KDIM  4096   // inner K of all projections

// ---------------- scratch (zero-init .bss, no runtime allocation) ----------
__device__ float g_q[(size_t)MROWS * DIM];
__device__ float g_k[(size_t)MROWS * KVDIM];
__device__ float g_v[(size_t)MROWS * KVDIM];
__device__ float g_attn[(size_t)MROWS * DIM];

// fp16 GEMM operands: A-side exact (hi+lo planes), B-side single rounding
__device__ __half g_xh [(size_t)MROWS * KDIM];
__device__ __half g_xl [(size_t)MROWS * KDIM];
__device__ __half g_ah [(size_t)MROWS * KDIM];
__device__ __half g_al [(size_t)MROWS * KDIM];
__device__ __half g_wqh[(size_t)DIM   * KDIM];
__device__ __half g_wkh[(size_t)KVDIM * KDIM];
__device__ __half g_wvh[(size_t)KVDIM * KDIM];
__device__ __half g_woh[(size_t)DIM   * KDIM];

// attention split operands (bf16 3-term, proven)
__device__ uint16_t g_qs2[(size_t)BATCH * NH  * SEQ * 384];
__device__ uint16_t g_ks2[(size_t)BATCH * NKV * SEQ * 384];
__device__ uint16_t g_vs2[(size_t)BATCH * NKV * (3*SEQ) * HD];

// ---------------- helpers ---------------------------------------------------
__device__ __forceinline__ uint32_t smem_u32(const void* p) {
    return (uint32_t)__cvta_generic_to_shared(p);
}
__device__ __forceinline__ void cp_async16(uint32_t dst, const void* src) {
    asm volatile("cp.async.cg.shared.global [%0], [%1], 16;" :: "r"(dst), "l"(src) : "memory");
}
__device__ __forceinline__ void cp_commit() {
    asm volatile("cp.async.commit_group;" ::: "memory");
}

#define LDSM_X4(r0, r1, r2, r3, addr) \
    asm volatile("ldmatrix.sync.aligned.m8n8.x4.shared.b16 {%0,%1,%2,%3}, [%4];" \
                 : "=r"(r0), "=r"(r1), "=r"(r2), "=r"(r3) : "r"(addr))

#define LDSM_X4_T(r0, r1, r2, r3, addr) \
    asm volatile("ldmatrix.sync.aligned.m8n8.x4.trans.shared.b16 {%0,%1,%2,%3}, [%4];" \
                 : "=r"(r0), "=r"(r1), "=r"(r2), "=r"(r3) : "r"(addr))

#define MMA_BF16(d, a, b0v, b1v) \
    asm volatile("mma.sync.aligned.m16n8k16.row.col.f32.bf16.bf16.f32 " \
                 "{%0,%1,%2,%3}, {%4,%5,%6,%7}, {%8,%9}, {%0,%1,%2,%3};" \
                 : "+f"((d)[0]), "+f"((d)[1]), "+f"((d)[2]), "+f"((d)[3]) \
                 : "r"((a)[0]), "r"((a)[1]), "r"((a)[2]), "r"((a)[3]), \
                   "r"(b0v), "r"(b1v))

#define MMA_F16(d, a, b0v, b1v) \
    asm volatile("mma.sync.aligned.m16n8k16.row.col.f32.f16.f16.f32 " \
                 "{%0,%1,%2,%3}, {%4,%5,%6,%7}, {%8,%9}, {%0,%1,%2,%3};" \
                 : "+f"((d)[0]), "+f"((d)[1]), "+f"((d)[2]), "+f"((d)[3]) \
                 : "r"((a)[0]), "r"((a)[1]), "r"((a)[2]), "r"((a)[3]), \
                   "r"(b0v), "r"(b1v))

__device__ __forceinline__ void split2(float f, uint16_t& hb, uint16_t& lb) {
    __nv_bfloat16 hi = __float2bfloat16_rn(f);
    __nv_bfloat16 lo = __float2bfloat16_rn(f - __bfloat162float(hi));
    hb = __bfloat16_as_ushort(hi);
    lb = __bfloat16_as_ushort(lo);
}

// ---------------------------------------------------------------------------
// A-side split: fp32 -> fp16 (hi, lo) planes. Fully coalesced.
// ---------------------------------------------------------------------------
__global__ void __launch_bounds__(256) split_a_f16(
    const float* __restrict__ src, __half* __restrict__ hi, __half* __restrict__ lo)
{
    size_t t = (size_t)blockIdx.x * 256 + threadIdx.x;
    float4 v0 = *(const float4*)&src[t * 8];
    float4 v1 = *(const float4*)&src[t * 8 + 4];
    float f[8] = {v0.x, v0.y, v0.z, v0.w, v1.x, v1.y, v1.z, v1.w};
    __align__(16) __half h[8], l[8];
#pragma unroll
    for (int j = 0; j < 8; j++) {
        h[j] = __float2half_rn(f[j]);
        l[j] = __float2half_rn(f[j] - __half2float(h[j]));
    }
    *(uint4*)&hi[t * 8] = *(uint4*)h;
    *(uint4*)&lo[t * 8] = *(uint4*)l;
}

// B-side: fp32 -> fp16 single rounding
__global__ void __launch_bounds__(256) cvt_f16(
    const float* __restrict__ src, __half* __restrict__ dst)
{
    size_t t = (size_t)blockIdx.x * 256 + threadIdx.x;
    float4 v0 = *(const float4*)&src[t * 8];
    float4 v1 = *(const float4*)&src[t * 8 + 4];
    float f[8] = {v0.x, v0.y, v0.z, v0.w, v1.x, v1.y, v1.z, v1.w};
    __align__(16) __half h[8];
#pragma unroll
    for (int j = 0; j < 8; j++) h[j] = __float2half_rn(f[j]);
    *(uint4*)&dst[t * 8] = *(uint4*)h;
}

// ---------------------------------------------------------------------------
// fp16 2-chain HMMA GEMM: C[m,n] = (Ahi[m,:]+Alo[m,:]) . Bh[n,:]
// CTA 128x128, 8 warps = 4m x 2n, warp 32x64. K=4096, BKC=32, 3-stage.
// Stage rows: [0,128) A_hi, [128,256) A_lo, [256,384) B. 80B stride.
// B-fragments shared by hi and lo chains; both accumulate into same d.
// ---------------------------------------------------------------------------
#define BKC         32
#define ROW_BYTES   80
#define STAGE_BYTES (384 * ROW_BYTES)   // 30720
#define NSTAGE      3
#define GSMEM       (NSTAGE * STAGE_BYTES)  // 92160
#define NITER       (KDIM / BKC)        // 128

__global__ void __launch_bounds__(256) gemm_f16(
    const __half* __restrict__ Ahi, const __half* __restrict__ Alo,
    const __half* __restrict__ Bh, float* __restrict__ C, int N)
{
    extern __shared__ __align__(1024) char smem[];
    const uint32_t sbase = smem_u32(smem);

    const int bm = blockIdx.y * 128;
    const int bn = blockIdx.x * 128;
    const int tid = threadIdx.x;
    const int wid = tid >> 5;
    const int lane = tid & 31;
    const int wm = wid & 3;
    const int wn = wid >> 2;

    const __half* gah = Ahi + (size_t)bm * KDIM;
    const __half* gal = Alo + (size_t)bm * KDIM;
    const __half* gb  = Bh  + (size_t)bn * KDIM;

    const int lc = tid & 3;          // 16B chunk within 64B
    const int lr = tid >> 2;         // 0..63

    auto load_stage = [&](int s, int chunk) {
        const uint32_t sa = sbase + (uint32_t)s * STAGE_BYTES;
        const size_t koff = (size_t)chunk * BKC + lc * 8;
#pragma unroll
        for (int j = 0; j < 6; j++) {
            int r = lr + j * 64;     // 0..383
            const __half* src;
            if (r < 128)      src = gah + (size_t)r * KDIM + koff;
            else if (r < 256) src = gal + (size_t)(r - 128) * KDIM + koff;
            else              src = gb  + (size_t)(r - 256) * KDIM + koff;
            cp_async16(sa + (uint32_t)(r * ROW_BYTES + lc * 16), src);
        }
        cp_commit();
    };

    float d[2][8][4];
#pragma unroll
    for (int mi = 0; mi < 2; mi++)
#pragma unroll
        for (int nj = 0; nj < 8; nj++)
#pragma unroll
            for (int q = 0; q < 4; q++) d[mi][nj][q] = 0.0f;

    const int grp  = lane >> 3;
    const int lrow = lane & 7;
    const int a_r = lrow + ((grp & 1) << 3);
    const int a_c = (grp >> 1) << 3;
    const int b_r = lrow + ((grp >> 1) << 3);
    const int b_c = (grp & 1) << 3;

    load_stage(0, 0);
    load_stage(1, 1);

    for (int i = 0; i < NITER; i++) {
        const int s = i % NSTAGE;
        asm volatile("cp.async.wait_group 1;" ::: "memory");
        __syncthreads();
        if (i + 2 < NITER) load_stage((i + 2) % NSTAGE, i + 2);
        else cp_commit();

        const uint32_t stg = sbase + (uint32_t)s * STAGE_BYTES;
        const uint32_t aHB = stg;                       // A_hi rows 0..127
        const uint32_t aLB = stg + 128 * ROW_BYTES;     // A_lo rows
        const uint32_t bB  = stg + 256 * ROW_BYTES;     // B rows
#pragma unroll
        for (int step = 0; step < 2; step++) {
            uint32_t bfr[4][4];
#pragma unroll
            for (int njp = 0; njp < 4; njp++) {
                uint32_t addr = bB + (uint32_t)((wn * 64 + njp * 16 + b_r) * ROW_BYTES
                                                + (step * 16 + b_c) * 2);
                LDSM_X4(bfr[njp][0], bfr[njp][1], bfr[njp][2], bfr[njp][3], addr);
            }
            uint32_t af[2][4];
            // hi chain
#pragma unroll
            for (int mi = 0; mi < 2; mi++) {
                uint32_t addr = aHB + (uint32_t)((wm * 32 + mi * 16 + a_r) * ROW_BYTES
                                                 + (step * 16 + a_c) * 2);
                LDSM_X4(af[mi][0], af[mi][1], af[mi][2], af[mi][3], addr);
            }
#pragma unroll
            for (int njp = 0; njp < 4; njp++)
#pragma unroll
                for (int mi = 0; mi < 2; mi++) {
                    MMA_F16(d[mi][2 * njp],     af[mi], bfr[njp][0], bfr[njp][1]);
                    MMA_F16(d[mi][2 * njp + 1], af[mi], bfr[njp][2], bfr[njp][3]);
                }
            // lo chain (reuse af regs, B frags still live)
#pragma unroll
            for (int mi = 0; mi < 2; mi++) {
                uint32_t addr = aLB + (uint32_t)((wm * 32 + mi * 16 + a_r) * ROW_BYTES
                                                 + (step * 16 + a_c) * 2);
                LDSM_X4(af[mi][0], af[mi][1], af[mi][2], af[mi][3], addr);
            }
#pragma unroll
            for (int njp = 0; njp < 4; njp++)
#pragma unroll
                for (int mi = 0; mi < 2; mi++) {
                    MMA_F16(d[mi][2 * njp],     af[mi], bfr[njp][0], bfr[njp][1]);
                    MMA_F16(d[mi][2 * njp + 1], af[mi], bfr[njp][2], bfr[njp][3]);
                }
        }
    }

    const int er = lane >> 2;
    const int ec = (lane & 3) * 2;
#pragma unroll
    for (int mi = 0; mi < 2; mi++) {
#pragma unroll
        for (int nj = 0; nj < 8; nj++) {
            int r0 = bm + wm * 32 + mi * 16 + er;
            int c0 = bn + wn * 64 + nj * 8 + ec;
            *(float2*)&C[(size_t)r0 * N + c0]       = make_float2(d[mi][nj][0], d[mi][nj][1]);
            *(float2*)&C[(size_t)(r0 + 8) * N + c0] = make_float2(d[mi][nj][2], d[mi][nj][3]);
        }
    }
}

// ---------------------------------------------------------------------------
// RoPE + split for Q/K (proven)
// ---------------------------------------------------------------------------
template <int ISQ>
__global__ void rope_split(const float* __restrict__ src, uint16_t* __restrict__ dst,
                           const float* __restrict__ fc, const float* __restrict__ fs)
{
    const int HEADS = ISQ ? NH : NKV;
    int gid = blockIdx.x * blockDim.x + threadIdx.x;
    int part = gid & 15;
    int row  = gid >> 4;
    int s = row & (SEQ - 1);
    int bh = row >> 11;
    int h = bh % HEADS;
    int b = bh / HEADS;
    const float scale = ISQ ? 0.08838834764831845f : 1.0f;

    const float* in = src + ((size_t)(b * SEQ + s)) * (HEADS * HD) + h * HD + part * 8;
    float vals[8];
    *(float4*)&vals[0] = *(const float4*)&in[0];
    *(float4*)&vals[4] = *(const float4*)&in[4];

    __align__(16) uint16_t o[24];
#pragma unroll
    for (int p = 0; p < 4; p++) {
        int i = part * 4 + p;
        float c  = fc[s * 64 + i];
        float sn = fs[s * 64 + i];
        float xr = vals[2 * p], xi = vals[2 * p + 1];
        float rr = (xr * c - xi * sn) * scale;
        float ri = (xr * sn + xi * c) * scale;
        float f2[2] = {rr, ri};
#pragma unroll
        for (int e = 0; e < 2; e++) {
            uint16_t hb, lb;
            split2(f2[e], hb, lb);
            int j = p * 2 + e;
            if (ISQ) { o[3*j] = hb; o[3*j+1] = lb; o[3*j+2] = hb; }
            else     { o[3*j] = hb; o[3*j+1] = hb; o[3*j+2] = lb; }
        }
    }
    uint4* dp = (uint4*)(dst + (size_t)row * 384 + part * 24);
    dp[0] = *(uint4*)&o[0];
    dp[1] = *(uint4*)&o[8];
    dp[2] = *(uint4*)&o[16];
}

__global__ void split_v_kernel(const float* __restrict__ src, uint16_t* __restrict__ dst)
{
    int gid = blockIdx.x * blockDim.x + threadIdx.x;
    int part = gid & 15;
    int row  = gid >> 4;
    int t = row & (SEQ - 1);
    int bkv = row >> 11;
    int kv = bkv & (NKV - 1);
    int b = bkv >> 3;

    const float* in = src + ((size_t)(b * SEQ + t)) * KVDIM + kv * HD + part * 8;
    float vals[8];
    *(float4*)&vals[0] = *(const float4*)&in[0];
    *(float4*)&vals[4] = *(const float4*)&in[4];

    __align__(16) uint16_t hi8[8], lo8[8];
#pragma unroll
    for (int j = 0; j < 8; j++) {
        uint16_t hb, lb;
        split2(vals[j], hb, lb);
        hi8[j] = hb; lo8[j] = lb;
    }
    uint16_t* out = dst + ((size_t)bkv * (3 * SEQ) + 3 * t) * HD + part * 8;
    *(uint4*)&out[0]        = *(uint4*)&hi8[0];
    *(uint4*)&out[HD]       = *(uint4*)&hi8[0];
    *(uint4*)&out[2 * HD]   = *(uint4*)&lo8[0];
}

// ---------------------------------------------------------------------------
// HMMA causal flash attention (R9, proven: bf16 3-term + K/V prefetch)
// ---------------------------------------------------------------------------
#define SQ_STR   784
#define SK_STR   784
#define SV_STR   272
#define SP_STR   400
#define SQ_OFF   0
#define SK_OFF   50176
#define SV_OFF   100352
#define SP_OFF   152576
#define ATT_SMEM 178176

__global__ void __launch_bounds__(256) attn_mma(
    const uint16_t* __restrict__ Qs, const uint16_t* __restrict__ Ks,
    const uint16_t* __restrict__ Vs, float* __restrict__ Oout)
{
    extern __shared__ __align__(1024) char smem[];
    const uint32_t sQ = smem_u32(smem) + SQ_OFF;
    const uint32_t sK = smem_u32(smem) + SK_OFF;
    const uint32_t sV = smem_u32(smem) + SV_OFF;
    const uint32_t sP = smem_u32(smem) + SP_OFF;
    float* mergeO = (float*)smem;
    float* mergeM = (float*)(smem + 32768);
    float* mergeL = (float*)(smem + 32768 + 256);

    const int qi = (SEQ / 64 - 1) - blockIdx.x;
    const int bh = blockIdx.y;
    const int b = bh >> 5, h = bh & 31, kvh = h >> 2;
    const int q0 = qi * 64;
    const int tid = threadIdx.x;
    const int wid = tid >> 5, lane = tid & 31;
    const int wm = wid & 3, wn = wid >> 2;
    const int grp = lane >> 3, lrow = lane & 7;

    const uint16_t* gk = Ks + ((size_t)(b * NKV + kvh) * SEQ) * 384;
    const uint16_t* gv = Vs + ((size_t)(b * NKV + kvh) * (3 * SEQ)) * HD;

    auto load_k = [&](int t0) {
#pragma unroll
        for (int j = 0; j < 12; j++) {
            int id = tid + j * 256;
            int r = id / 48, c = id % 48;
            cp_async16(sK + (uint32_t)(r * SK_STR + c * 16),
                       gk + ((size_t)(t0 + r)) * 384 + c * 8);
        }
        cp_commit();
    };
    auto load_v = [&](int t0) {
#pragma unroll
        for (int j = 0; j < 12; j++) {
            int id = tid + j * 256;
            int r = id / 16, c = id % 16;
            cp_async16(sV + (uint32_t)(r * SV_STR + c * 16),
                       gv + ((size_t)(t0 * 3 + r)) * HD + c * 8);
        }
        cp_commit();
    };

    const uint16_t* gq = Qs + ((size_t)(b * NH + h) * SEQ + q0) * 384;
#pragma unroll
    for (int j = 0; j < 12; j++) {
        int id = tid + j * 256;
        int r = id / 48, c = id % 48;
        cp_async16(sQ + (uint32_t)(r * SQ_STR + c * 16), gq + (size_t)r * 384 + c * 8);
    }
    cp_commit();
    load_k(0);
    load_v(0);

    float m0 = -1e30f, m1 = -1e30f, l0 = 0.0f, l1 = 0.0f;
    float Oc[16][4];
#pragma unroll
    for (int j = 0; j < 16; j++)
#pragma unroll
        for (int q = 0; q < 4; q++) Oc[j][q] = 0.0f;

    const int ra = wm * 16 + (lane >> 2);

    for (int kt = 0; kt <= qi; kt++) {
        asm volatile("cp.async.wait_group 0;" ::: "memory");
        __syncthreads();

        float Sa[4][4];
#pragma unroll
        for (int nt = 0; nt < 4; nt++)
#pragma unroll
            for (int q = 0; q < 4; q++) Sa[nt][q] = 0.0f;

#pragma unroll
        for (int ks = 0; ks < 24; ks++) {
            uint32_t A[4];
            uint32_t aaddr = sQ + (uint32_t)((wm * 16 + lrow + ((grp & 1) << 3)) * SQ_STR
                                             + (ks * 16 + ((grp >> 1) << 3)) * 2);
            LDSM_X4(A[0], A[1], A[2], A[3], aaddr);
#pragma unroll
            for (int ntp = 0; ntp < 2; ntp++) {
                uint32_t b0, b1, b2, b3;
                uint32_t baddr = sK + (uint32_t)((wn * 32 + ntp * 16 + lrow + ((grp >> 1) << 3)) * SK_STR
                                                 + (ks * 16 + ((grp & 1) << 3)) * 2);
                LDSM_X4(b0, b1, b2, b3, baddr);
                MMA_BF16(Sa[2 * ntp],     A, b0, b1);
                MMA_BF16(Sa[2 * ntp + 1], A, b2, b3);
            }
        }

        __syncthreads();
        if (kt < qi) load_k((kt + 1) * 64);

        if (kt == qi) {
#pragma unroll
            for (int nt = 0; nt < 4; nt++) {
                int tb = wn * 32 + nt * 8 + 2 * (lane & 3);
                if (tb     > ra)     Sa[nt][0] = -1e30f;
                if (tb + 1 > ra)     Sa[nt][1] = -1e30f;
                if (tb     > ra + 8) Sa[nt][2] = -1e30f;
                if (tb + 1 > ra + 8) Sa[nt][3] = -1e30f;
            }
        }

        float hm0 = -1e30f, hm1 = -1e30f;
#pragma unroll
        for (int nt = 0; nt < 4; nt++) {
            hm0 = fmaxf(hm0, fmaxf(Sa[nt][0], Sa[nt][1]));
            hm1 = fmaxf(hm1, fmaxf(Sa[nt][2], Sa[nt][3]));
        }
        hm0 = fmaxf(hm0, __shfl_xor_sync(0xffffffffu, hm0, 1));
        hm0 = fmaxf(hm0, __shfl_xor_sync(0xffffffffu, hm0, 2));
        hm1 = fmaxf(hm1, __shfl_xor_sync(0xffffffffu, hm1, 1));
        hm1 = fmaxf(hm1, __shfl_xor_sync(0xffffffffu, hm1, 2));

        float mn0 = fmaxf(m0, hm0), mn1 = fmaxf(m1, hm1);
        float al0 = __expf(m0 - mn0), al1 = __expf(m1 - mn1);
        m0 = mn0; m1 = mn1;

        float hs0 = 0.0f, hs1 = 0.0f;
#pragma unroll
        for (int nt = 0; nt < 4; nt++) {
            Sa[nt][0] = __expf(Sa[nt][0] - mn0); hs0 += Sa[nt][0];
            Sa[nt][1] = __expf(Sa[nt][1] - mn0); hs0 += Sa[nt][1];
            Sa[nt][2] = __expf(Sa[nt][2] - mn1); hs1 += Sa[nt][2];
            Sa[nt][3] = __expf(Sa[nt][3] - mn1); hs1 += Sa[nt][3];
        }
        hs0 += __shfl_xor_sync(0xffffffffu, hs0, 1);
        hs0 += __shfl_xor_sync(0xffffffffu, hs0, 2);
        hs1 += __shfl_xor_sync(0xffffffffu, hs1, 1);
        hs1 += __shfl_xor_sync(0xffffffffu, hs1, 2);
        l0 = l0 * al0 + hs0;
        l1 = l1 * al1 + hs1;
#pragma unroll
        for (int j = 0; j < 16; j++) {
            Oc[j][0] *= al0; Oc[j][1] *= al0;
            Oc[j][2] *= al1; Oc[j][3] *= al1;
        }

        __syncwarp();
#pragma unroll
        for (int nt = 0; nt < 4; nt++) {
            int tl0 = wn * 32 + nt * 8 + 2 * (lane & 3);
#pragma unroll
            for (int q = 0; q < 4; q++) {
                int row = ra + ((q >> 1) << 3);
                int t = tl0 + (q & 1);
                float p = Sa[nt][q];
                uint16_t hb, lb;
                split2(p, hb, lb);
                uint32_t ad = sP + (uint32_t)(row * SP_STR + t * 6);
                asm volatile("st.shared.u16 [%0], %1;" :: "r"(ad),     "h"(hb));
                asm volatile("st.shared.u16 [%0], %1;" :: "r"(ad + 2), "h"(lb));
                asm volatile("st.shared.u16 [%0], %1;" :: "r"(ad + 4), "h"(hb));
            }
        }
        __syncwarp();

#pragma unroll
        for (int ks2 = 0; ks2 < 6; ks2++) {
            uint32_t A[4];
            uint32_t aaddr = sP + (uint32_t)((wm * 16 + lrow + ((grp & 1) << 3)) * SP_STR
                                             + (wn * 96 + ks2 * 16 + ((grp >> 1) << 3)) * 2);
            LDSM_X4(A[0], A[1], A[2], A[3], aaddr);
#pragma unroll
            for (int ntp = 0; ntp < 8; ntp++) {
                uint32_t b0, b1, b2, b3;
                uint32_t baddr = sV + (uint32_t)((wn * 96 + ks2 * 16 + lrow + ((grp & 1) << 3)) * SV_STR
                                                 + (ntp * 16 + ((grp >> 1) << 3)) * 2);
                LDSM_X4_T(b0, b1, b2, b3, baddr);
                MMA_BF16(Oc[2 * ntp],     A, b0, b1);
                MMA_BF16(Oc[2 * ntp + 1], A, b2, b3);
            }
        }

        __syncthreads();
        if (kt < qi) load_v((kt + 1) * 64);
    }

    __syncthreads();
    if (wn == 1) {
#pragma unroll
        for (int nt = 0; nt < 16; nt++) {
            int col = nt * 8 + 2 * (lane & 3);
            *(float2*)&mergeO[ra * 128 + col]       = make_float2(Oc[nt][0], Oc[nt][1]);
            *(float2*)&mergeO[(ra + 8) * 128 + col] = make_float2(Oc[nt][2], Oc[nt][3]);
        }
        if ((lane & 3) == 0) {
            mergeM[ra] = m0;     mergeM[ra + 8] = m1;
            mergeL[ra] = l0;     mergeL[ra + 8] = l1;
        }
    }
    __syncthreads();
    if (wn == 0) {
        float M1a = mergeM[ra],     L1a = mergeL[ra];
        float M1b = mergeM[ra + 8], L1b = mergeL[ra + 8];
        float Ma = fmaxf(m0, M1a);
        float w0a = __expf(m0 - Ma), w1a = __expf(M1a - Ma);
        float inva = 1.0f / (l0 * w0a + L1a * w1a);
        float Mb = fmaxf(m1, M1b);
        float w0b = __expf(m1 - Mb), w1b = __expf(M1b - Mb);
        float invb = 1.0f / (l1 * w0b + L1b * w1b);

        size_t obase = ((size_t)(b * SEQ + q0)) * DIM + h * HD;
#pragma unroll
        for (int nt = 0; nt < 16; nt++) {
            int col = nt * 8 + 2 * (lane & 3);
            float2 o1a = *(float2*)&mergeO[ra * 128 + col];
            float2 o1b = *(float2*)&mergeO[(ra + 8) * 128 + col];
            float2 oa = make_float2((Oc[nt][0] * w0a + o1a.x * w1a) * inva,
                                    (Oc[nt][1] * w0a + o1a.y * w1a) * inva);
            float2 ob = make_float2((Oc[nt][2] * w0b + o1b.x * w1b) * invb,
                                    (Oc[nt][3] * w0b + o1b.y * w1b) * invb);
            *(float2*)&Oout[obase + (size_t)ra * DIM + col]       = oa;
            *(float2*)&Oout[obase + (size_t)(ra + 8) * DIM + col] = ob;
        }
    }
}

// ---------------------------------------------------------------------------
extern "C" void kernel_launch(void* const* d_in, const int* in_sizes, int n_in,
                              void* d_out, int out_size)
{
    const float* x  = (const float*)d_in[0];
    const float* wq = (const float*)d_in[1];
    const float* wk = (const float*)d_in[2];
    const float* wv = (const float*)d_in[3];
    const float* wo = (const float*)d_in[4];
    const float* fc = (const float*)d_in[5];
    const float* fs = (const float*)d_in[6];
    float* out = (float*)d_out;

    float *qp, *kp, *vp, *ap;
    __half *xh, *xl, *ah, *al, *wqh, *wkh, *wvh, *woh;
    uint16_t *qs2, *ks2, *vs2;
    cudaGetSymbolAddress((void**)&qp, g_q);
    cudaGetSymbolAddress((void**)&kp, g_k);
    cudaGetSymbolAddress((void**)&vp, g_v);
    cudaGetSymbolAddress((void**)&ap, g_attn);
    cudaGetSymbolAddress((void**)&xh, g_xh);
    cudaGetSymbolAddress((void**)&xl, g_xl);
    cudaGetSymbolAddress((void**)&ah, g_ah);
    cudaGetSymbolAddress((void**)&al, g_al);
    cudaGetSymbolAddress((void**)&wqh, g_wqh);
    cudaGetSymbolAddress((void**)&wkh, g_wkh);
    cudaGetSymbolAddress((void**)&wvh, g_wvh);
    cudaGetSymbolAddress((void**)&woh, g_woh);
    cudaGetSymbolAddress((void**)&qs2, g_qs2);
    cudaGetSymbolAddress((void**)&ks2, g_ks2);
    cudaGetSymbolAddress((void**)&vs2, g_vs2);

    cudaFuncSetAttribute(gemm_f16, cudaFuncAttributeMaxDynamicSharedMemorySize, GSMEM);
    cudaFuncSetAttribute(attn_mma, cudaFuncAttributeMaxDynamicSharedMemorySize, ATT_SMEM);

    // Operand conversion
    split_a_f16<<<(MROWS * KDIM / 8) / 256, 256>>>(x, xh, xl);
    cvt_f16<<<(DIM   * KDIM / 8) / 256, 256>>>(wq, wqh);
    cvt_f16<<<(KVDIM * KDIM / 8) / 256, 256>>>(wk, wkh);
    cvt_f16<<<(KVDIM * KDIM / 8) / 256, 256>>>(wv, wvh);
    cvt_f16<<<(DIM   * KDIM / 8) / 256, 256>>>(wo, woh);

    // QKV projections (fp16 2-chain HMMA)
    gemm_f16<<<dim3(DIM   / 128, MROWS / 128), 256, GSMEM>>>(xh, xl, wqh, qp, DIM);
    gemm_f16<<<dim3(KVDIM / 128, MROWS / 128), 256, GSMEM>>>(xh, xl, wkh, kp, KVDIM);
    gemm_f16<<<dim3(KVDIM / 128, MROWS / 128), 256, GSMEM>>>(xh, xl, wvh, vp, KVDIM);

    // RoPE + split for attention operands
    rope_split<1><<<(BATCH * NH  * SEQ * 16) / 256, 256>>>(qp, qs2, fc, fs);
    rope_split<0><<<(BATCH * NKV * SEQ * 16) / 256, 256>>>(kp, ks2, fc, fs);
    split_v_kernel<<<(BATCH * NKV * SEQ * 16) / 256, 256>>>(vp, vs2);

    // HMMA flash attention (bf16 3-term, K/V prefetch)
    attn_mma<<<dim3(SEQ / 64, BATCH * NH), 256, ATT_SMEM>>>(qs2, ks2, vs2, ap);

    // Output projection
    split_a_f16<<<(MROWS * KDIM / 8) / 256, 256>>>(ap, ah, al);
    gemm_f16<<<dim3(DIM / 128, MROWS / 128), 256, GSMEM>>>(ah, al, woh, out, DIM);
}

// round 12
// speedup vs baseline: 1.3861x; 1.3861x over previous
#include <cuda_runtime.h>
#include <cuda_fp16.h>
#include <cuda_bf16.h>
#include <math.h>
#include <stdint.h>

#define BATCH 2
#define SEQ   2048
#define DIM   4096
#define NH    32
#define NKV   8
#define HD    128
#define MROWS 4096   // BATCH*SEQ
#define KVDIM 1024   // NKV*HD
#define KDIM  4096
#define K2    (2 * KDIM)   // 8192: fp16 (hi,lo)x(b,b) interleaved K

// ---------------- scratch (zero-init .bss, no runtime allocation) ----------
__device__ float g_q[(size_t)MROWS * DIM];
__device__ float g_k[(size_t)MROWS * KVDIM];
__device__ float g_v[(size_t)MROWS * KVDIM];
__device__ float g_attn[(size_t)MROWS * DIM];

// fp16 interleaved GEMM operands
__device__ __half g_xs [(size_t)MROWS * K2];   // x:  (hi,lo) interleaved
__device__ __half g_as [(size_t)MROWS * K2];   // attn-out: (hi,lo)
__device__ __half g_wqs[(size_t)DIM   * K2];   // weights: (b,b) duplicated
__device__ __half g_wks[(size_t)KVDIM * K2];
__device__ __half g_wvs[(size_t)KVDIM * K2];
__device__ __half g_wos[(size_t)DIM   * K2];

// attention split operands (bf16 3-term, proven)
__device__ uint16_t g_qs2[(size_t)BATCH * NH  * SEQ * 384];
__device__ uint16_t g_ks2[(size_t)BATCH * NKV * SEQ * 384];
__device__ uint16_t g_vs2[(size_t)BATCH * NKV * (3*SEQ) * HD];

// ---------------- helpers ---------------------------------------------------
__device__ __forceinline__ uint32_t smem_u32(const void* p) {
    return (uint32_t)__cvta_generic_to_shared(p);
}
__device__ __forceinline__ void cp_async16(uint32_t dst, const void* src) {
    asm volatile("cp.async.cg.shared.global [%0], [%1], 16;" :: "r"(dst), "l"(src) : "memory");
}
__device__ __forceinline__ void cp_commit() {
    asm volatile("cp.async.commit_group;" ::: "memory");
}

#define LDSM_X4(r0, r1, r2, r3, addr) \
    asm volatile("ldmatrix.sync.aligned.m8n8.x4.shared.b16 {%0,%1,%2,%3}, [%4];" \
                 : "=r"(r0), "=r"(r1), "=r"(r2), "=r"(r3) : "r"(addr))

#define LDSM_X4_T(r0, r1, r2, r3, addr) \
    asm volatile("ldmatrix.sync.aligned.m8n8.x4.trans.shared.b16 {%0,%1,%2,%3}, [%4];" \
                 : "=r"(r0), "=r"(r1), "=r"(r2), "=r"(r3) : "r"(addr))

#define MMA_BF16(d, a, b0v, b1v) \
    asm volatile("mma.sync.aligned.m16n8k16.row.col.f32.bf16.bf16.f32 " \
                 "{%0,%1,%2,%3}, {%4,%5,%6,%7}, {%8,%9}, {%0,%1,%2,%3};" \
                 : "+f"((d)[0]), "+f"((d)[1]), "+f"((d)[2]), "+f"((d)[3]) \
                 : "r"((a)[0]), "r"((a)[1]), "r"((a)[2]), "r"((a)[3]), \
                   "r"(b0v), "r"(b1v))

#define MMA_F16(d, a, b0v, b1v) \
    asm volatile("mma.sync.aligned.m16n8k16.row.col.f32.f16.f16.f32 " \
                 "{%0,%1,%2,%3}, {%4,%5,%6,%7}, {%8,%9}, {%0,%1,%2,%3};" \
                 : "+f"((d)[0]), "+f"((d)[1]), "+f"((d)[2]), "+f"((d)[3]) \
                 : "r"((a)[0]), "r"((a)[1]), "r"((a)[2]), "r"((a)[3]), \
                   "r"(b0v), "r"(b1v))

__device__ __forceinline__ void split2(float f, uint16_t& hb, uint16_t& lb) {
    __nv_bfloat16 hi = __float2bfloat16_rn(f);
    __nv_bfloat16 lo = __float2bfloat16_rn(f - __bfloat162float(hi));
    hb = __bfloat16_as_ushort(hi);
    lb = __bfloat16_as_ushort(lo);
}

// ---------------------------------------------------------------------------
// A-side: fp32 -> interleaved fp16 (hi,lo) pairs.  8 floats -> 16 halves.
// ---------------------------------------------------------------------------
__global__ void __launch_bounds__(256) split_a2(
    const float* __restrict__ src, __half* __restrict__ dst)
{
    size_t t = (size_t)blockIdx.x * 256 + threadIdx.x;
    float4 v0 = *(const float4*)&src[t * 8];
    float4 v1 = *(const float4*)&src[t * 8 + 4];
    float f[8] = {v0.x, v0.y, v0.z, v0.w, v1.x, v1.y, v1.z, v1.w};
    __align__(16) __half o[16];
#pragma unroll
    for (int j = 0; j < 8; j++) {
        __half h = __float2half_rn(f[j]);
        __half l = __float2half_rn(f[j] - __half2float(h));
        o[2*j] = h; o[2*j+1] = l;
    }
    uint4* dp = (uint4*)&dst[t * 16];
    dp[0] = *(uint4*)&o[0];
    dp[1] = *(uint4*)&o[8];
}

// B-side: fp32 -> interleaved (b,b) duplicated fp16 pairs.
__global__ void __launch_bounds__(256) cvt_b2(
    const float* __restrict__ src, __half* __restrict__ dst)
{
    size_t t = (size_t)blockIdx.x * 256 + threadIdx.x;
    float4 v0 = *(const float4*)&src[t * 8];
    float4 v1 = *(const float4*)&src[t * 8 + 4];
    float f[8] = {v0.x, v0.y, v0.z, v0.w, v1.x, v1.y, v1.z, v1.w};
    __align__(16) __half o[16];
#pragma unroll
    for (int j = 0; j < 8; j++) {
        __half h = __float2half_rn(f[j]);
        o[2*j] = h; o[2*j+1] = h;
    }
    uint4* dp = (uint4*)&dst[t * 16];
    dp[0] = *(uint4*)&o[0];
    dp[1] = *(uint4*)&o[8];
}

// ---------------------------------------------------------------------------
// fp16 HMMA GEMM — EXACT R9 structure (128x128 CTA, warp 32x64, 4-stage,
// 80B rows, 2 CTAs/SM); only K3->K2 and bf16->f16 changed.
// ---------------------------------------------------------------------------
#define BKC         32
#define ROW_BYTES   80
#define STAGE_BYTES (256 * ROW_BYTES)
#define NSTAGE      4
#define GSMEM       (NSTAGE * STAGE_BYTES)
#define NITER       (K2 / BKC)          // 256

__global__ void __launch_bounds__(256) gemm_hmma(
    const __half* __restrict__ A, const __half* __restrict__ Bm,
    float* __restrict__ C, int M, int N)
{
    extern __shared__ __align__(1024) char smem[];
    const uint32_t sbase = smem_u32(smem);

    const int bm = blockIdx.y * 128;
    const int bn = blockIdx.x * 128;
    const int tid = threadIdx.x;
    const int wid = tid >> 5;
    const int lane = tid & 31;
    const int wm = wid & 3;
    const int wn = wid >> 2;

    const __half* ga0 = A  + (size_t)bm * K2;
    const __half* gb0 = Bm + (size_t)bn * K2;

    const int lc = tid & 3;
    const int lr = tid >> 2;

    auto load_stage = [&](int s, int chunk) {
        const uint32_t sa = sbase + (uint32_t)s * STAGE_BYTES;
        const size_t koff = (size_t)chunk * BKC + lc * 8;
#pragma unroll
        for (int j = 0; j < 4; j++) {
            int r = lr + j * 64;
            const __half* src = (r < 128)
                ? ga0 + (size_t)r * K2 + koff
                : gb0 + (size_t)(r - 128) * K2 + koff;
            cp_async16(sa + (uint32_t)(r * ROW_BYTES + lc * 16), src);
        }
        cp_commit();
    };

    float d[2][8][4];
#pragma unroll
    for (int mi = 0; mi < 2; mi++)
#pragma unroll
        for (int nj = 0; nj < 8; nj++)
#pragma unroll
            for (int q = 0; q < 4; q++) d[mi][nj][q] = 0.0f;

    const int grp  = lane >> 3;
    const int lrow = lane & 7;
    const int a_r = lrow + ((grp & 1) << 3);
    const int a_c = (grp >> 1) << 3;
    const int b_r = lrow + ((grp >> 1) << 3);
    const int b_c = (grp & 1) << 3;

    load_stage(0, 0);
    load_stage(1, 1);
    load_stage(2, 2);

    for (int i = 0; i < NITER; i++) {
        const int s = i & (NSTAGE - 1);
        asm volatile("cp.async.wait_group %0;" :: "n"(NSTAGE - 2) : "memory");
        __syncthreads();
        if (i + 3 < NITER) load_stage((i + 3) & (NSTAGE - 1), i + 3);
        else cp_commit();

        const uint32_t aB = sbase + (uint32_t)s * STAGE_BYTES;
        const uint32_t bB = aB + 128 * ROW_BYTES;
#pragma unroll
        for (int step = 0; step < 2; step++) {
            uint32_t af[2][4];
#pragma unroll
            for (int mi = 0; mi < 2; mi++) {
                uint32_t addr = aB + (uint32_t)((wm * 32 + mi * 16 + a_r) * ROW_BYTES
                                                + (step * 16 + a_c) * 2);
                LDSM_X4(af[mi][0], af[mi][1], af[mi][2], af[mi][3], addr);
            }
#pragma unroll
            for (int njp = 0; njp < 4; njp++) {
                uint32_t b0, b1, b2, b3;
                uint32_t addr = bB + (uint32_t)((wn * 64 + njp * 16 + b_r) * ROW_BYTES
                                                + (step * 16 + b_c) * 2);
                LDSM_X4(b0, b1, b2, b3, addr);
#pragma unroll
                for (int mi = 0; mi < 2; mi++) {
                    MMA_F16(d[mi][2 * njp],     af[mi], b0, b1);
                    MMA_F16(d[mi][2 * njp + 1], af[mi], b2, b3);
                }
            }
        }
    }

    const int er = lane >> 2;
    const int ec = (lane & 3) * 2;
#pragma unroll
    for (int mi = 0; mi < 2; mi++) {
#pragma unroll
        for (int nj = 0; nj < 8; nj++) {
            int r0 = bm + wm * 32 + mi * 16 + er;
            int c0 = bn + wn * 64 + nj * 8 + ec;
            *(float2*)&C[(size_t)r0 * N + c0]       = make_float2(d[mi][nj][0], d[mi][nj][1]);
            *(float2*)&C[(size_t)(r0 + 8) * N + c0] = make_float2(d[mi][nj][2], d[mi][nj][3]);
        }
    }
}

// ---------------------------------------------------------------------------
// RoPE + split for Q/K (proven)
// ---------------------------------------------------------------------------
template <int ISQ>
__global__ void rope_split(const float* __restrict__ src, uint16_t* __restrict__ dst,
                           const float* __restrict__ fc, const float* __restrict__ fs)
{
    const int HEADS = ISQ ? NH : NKV;
    int gid = blockIdx.x * blockDim.x + threadIdx.x;
    int part = gid & 15;
    int row  = gid >> 4;
    int s = row & (SEQ - 1);
    int bh = row >> 11;
    int h = bh % HEADS;
    int b = bh / HEADS;
    const float scale = ISQ ? 0.08838834764831845f : 1.0f;

    const float* in = src + ((size_t)(b * SEQ + s)) * (HEADS * HD) + h * HD + part * 8;
    float vals[8];
    *(float4*)&vals[0] = *(const float4*)&in[0];
    *(float4*)&vals[4] = *(const float4*)&in[4];

    __align__(16) uint16_t o[24];
#pragma unroll
    for (int p = 0; p < 4; p++) {
        int i = part * 4 + p;
        float c  = fc[s * 64 + i];
        float sn = fs[s * 64 + i];
        float xr = vals[2 * p], xi = vals[2 * p + 1];
        float rr = (xr * c - xi * sn) * scale;
        float ri = (xr * sn + xi * c) * scale;
        float f2[2] = {rr, ri};
#pragma unroll
        for (int e = 0; e < 2; e++) {
            uint16_t hb, lb;
            split2(f2[e], hb, lb);
            int j = p * 2 + e;
            if (ISQ) { o[3*j] = hb; o[3*j+1] = lb; o[3*j+2] = hb; }
            else     { o[3*j] = hb; o[3*j+1] = hb; o[3*j+2] = lb; }
        }
    }
    uint4* dp = (uint4*)(dst + (size_t)row * 384 + part * 24);
    dp[0] = *(uint4*)&o[0];
    dp[1] = *(uint4*)&o[8];
    dp[2] = *(uint4*)&o[16];
}

__global__ void split_v_kernel(const float* __restrict__ src, uint16_t* __restrict__ dst)
{
    int gid = blockIdx.x * blockDim.x + threadIdx.x;
    int part = gid & 15;
    int row  = gid >> 4;
    int t = row & (SEQ - 1);
    int bkv = row >> 11;
    int kv = bkv & (NKV - 1);
    int b = bkv >> 3;

    const float* in = src + ((size_t)(b * SEQ + t)) * KVDIM + kv * HD + part * 8;
    float vals[8];
    *(float4*)&vals[0] = *(const float4*)&in[0];
    *(float4*)&vals[4] = *(const float4*)&in[4];

    __align__(16) uint16_t hi8[8], lo8[8];
#pragma unroll
    for (int j = 0; j < 8; j++) {
        uint16_t hb, lb;
        split2(vals[j], hb, lb);
        hi8[j] = hb; lo8[j] = lb;
    }
    uint16_t* out = dst + ((size_t)bkv * (3 * SEQ) + 3 * t) * HD + part * 8;
    *(uint4*)&out[0]        = *(uint4*)&hi8[0];
    *(uint4*)&out[HD]       = *(uint4*)&hi8[0];
    *(uint4*)&out[2 * HD]   = *(uint4*)&lo8[0];
}

// ---------------------------------------------------------------------------
// HMMA causal flash attention (R9, proven: bf16 3-term + K/V prefetch)
// ---------------------------------------------------------------------------
#define SQ_STR   784
#define SK_STR   784
#define SV_STR   272
#define SP_STR   400
#define SQ_OFF   0
#define SK_OFF   50176
#define SV_OFF   100352
#define SP_OFF   152576
#define ATT_SMEM 178176

__global__ void __launch_bounds__(256) attn_mma(
    const uint16_t* __restrict__ Qs, const uint16_t* __restrict__ Ks,
    const uint16_t* __restrict__ Vs, float* __restrict__ Oout)
{
    extern __shared__ __align__(1024) char smem[];
    const uint32_t sQ = smem_u32(smem) + SQ_OFF;
    const uint32_t sK = smem_u32(smem) + SK_OFF;
    const uint32_t sV = smem_u32(smem) + SV_OFF;
    const uint32_t sP = smem_u32(smem) + SP_OFF;
    float* mergeO = (float*)smem;
    float* mergeM = (float*)(smem + 32768);
    float* mergeL = (float*)(smem + 32768 + 256);

    const int qi = (SEQ / 64 - 1) - blockIdx.x;
    const int bh = blockIdx.y;
    const int b = bh >> 5, h = bh & 31, kvh = h >> 2;
    const int q0 = qi * 64;
    const int tid = threadIdx.x;
    const int wid = tid >> 5, lane = tid & 31;
    const int wm = wid & 3, wn = wid >> 2;
    const int grp = lane >> 3, lrow = lane & 7;

    const uint16_t* gk = Ks + ((size_t)(b * NKV + kvh) * SEQ) * 384;
    const uint16_t* gv = Vs + ((size_t)(b * NKV + kvh) * (3 * SEQ)) * HD;

    auto load_k = [&](int t0) {
#pragma unroll
        for (int j = 0; j < 12; j++) {
            int id = tid + j * 256;
            int r = id / 48, c = id % 48;
            cp_async16(sK + (uint32_t)(r * SK_STR + c * 16),
                       gk + ((size_t)(t0 + r)) * 384 + c * 8);
        }
        cp_commit();
    };
    auto load_v = [&](int t0) {
#pragma unroll
        for (int j = 0; j < 12; j++) {
            int id = tid + j * 256;
            int r = id / 16, c = id % 16;
            cp_async16(sV + (uint32_t)(r * SV_STR + c * 16),
                       gv + ((size_t)(t0 * 3 + r)) * HD + c * 8);
        }
        cp_commit();
    };

    const uint16_t* gq = Qs + ((size_t)(b * NH + h) * SEQ + q0) * 384;
#pragma unroll
    for (int j = 0; j < 12; j++) {
        int id = tid + j * 256;
        int r = id / 48, c = id % 48;
        cp_async16(sQ + (uint32_t)(r * SQ_STR + c * 16), gq + (size_t)r * 384 + c * 8);
    }
    cp_commit();
    load_k(0);
    load_v(0);

    float m0 = -1e30f, m1 = -1e30f, l0 = 0.0f, l1 = 0.0f;
    float Oc[16][4];
#pragma unroll
    for (int j = 0; j < 16; j++)
#pragma unroll
        for (int q = 0; q < 4; q++) Oc[j][q] = 0.0f;

    const int ra = wm * 16 + (lane >> 2);

    for (int kt = 0; kt <= qi; kt++) {
        asm volatile("cp.async.wait_group 0;" ::: "memory");
        __syncthreads();

        float Sa[4][4];
#pragma unroll
        for (int nt = 0; nt < 4; nt++)
#pragma unroll
            for (int q = 0; q < 4; q++) Sa[nt][q] = 0.0f;

#pragma unroll
        for (int ks = 0; ks < 24; ks++) {
            uint32_t A[4];
            uint32_t aaddr = sQ + (uint32_t)((wm * 16 + lrow + ((grp & 1) << 3)) * SQ_STR
                                             + (ks * 16 + ((grp >> 1) << 3)) * 2);
            LDSM_X4(A[0], A[1], A[2], A[3], aaddr);
#pragma unroll
            for (int ntp = 0; ntp < 2; ntp++) {
                uint32_t b0, b1, b2, b3;
                uint32_t baddr = sK + (uint32_t)((wn * 32 + ntp * 16 + lrow + ((grp >> 1) << 3)) * SK_STR
                                                 + (ks * 16 + ((grp & 1) << 3)) * 2);
                LDSM_X4(b0, b1, b2, b3, baddr);
                MMA_BF16(Sa[2 * ntp],     A, b0, b1);
                MMA_BF16(Sa[2 * ntp + 1], A, b2, b3);
            }
        }

        __syncthreads();
        if (kt < qi) load_k((kt + 1) * 64);

        if (kt == qi) {
#pragma unroll
            for (int nt = 0; nt < 4; nt++) {
                int tb = wn * 32 + nt * 8 + 2 * (lane & 3);
                if (tb     > ra)     Sa[nt][0] = -1e30f;
                if (tb + 1 > ra)     Sa[nt][1] = -1e30f;
                if (tb     > ra + 8) Sa[nt][2] = -1e30f;
                if (tb + 1 > ra + 8) Sa[nt][3] = -1e30f;
            }
        }

        float hm0 = -1e30f, hm1 = -1e30f;
#pragma unroll
        for (int nt = 0; nt < 4; nt++) {
            hm0 = fmaxf(hm0, fmaxf(Sa[nt][0], Sa[nt][1]));
            hm1 = fmaxf(hm1, fmaxf(Sa[nt][2], Sa[nt][3]));
        }
        hm0 = fmaxf(hm0, __shfl_xor_sync(0xffffffffu, hm0, 1));
        hm0 = fmaxf(hm0, __shfl_xor_sync(0xffffffffu, hm0, 2));
        hm1 = fmaxf(hm1, __shfl_xor_sync(0xffffffffu, hm1, 1));
        hm1 = fmaxf(hm1, __shfl_xor_sync(0xffffffffu, hm1, 2));

        float mn0 = fmaxf(m0, hm0), mn1 = fmaxf(m1, hm1);
        float al0 = __expf(m0 - mn0), al1 = __expf(m1 - mn1);
        m0 = mn0; m1 = mn1;

        float hs0 = 0.0f, hs1 = 0.0f;
#pragma unroll
        for (int nt = 0; nt < 4; nt++) {
            Sa[nt][0] = __expf(Sa[nt][0] - mn0); hs0 += Sa[nt][0];
            Sa[nt][1] = __expf(Sa[nt][1] - mn0); hs0 += Sa[nt][1];
            Sa[nt][2] = __expf(Sa[nt][2] - mn1); hs1 += Sa[nt][2];
            Sa[nt][3] = __expf(Sa[nt][3] - mn1); hs1 += Sa[nt][3];
        }
        hs0 += __shfl_xor_sync(0xffffffffu, hs0, 1);
        hs0 += __shfl_xor_sync(0xffffffffu, hs0, 2);
        hs1 += __shfl_xor_sync(0xffffffffu, hs1, 1);
        hs1 += __shfl_xor_sync(0xffffffffu, hs1, 2);
        l0 = l0 * al0 + hs0;
        l1 = l1 * al1 + hs1;
#pragma unroll
        for (int j = 0; j < 16; j++) {
            Oc[j][0] *= al0; Oc[j][1] *= al0;
            Oc[j][2] *= al1; Oc[j][3] *= al1;
        }

        __syncwarp();
#pragma unroll
        for (int nt = 0; nt < 4; nt++) {
            int tl0 = wn * 32 + nt * 8 + 2 * (lane & 3);
#pragma unroll
            for (int q = 0; q < 4; q++) {
                int row = ra + ((q >> 1) << 3);
                int t = tl0 + (q & 1);
                float p = Sa[nt][q];
                uint16_t hb, lb;
                split2(p, hb, lb);
                uint32_t ad = sP + (uint32_t)(row * SP_STR + t * 6);
                asm volatile("st.shared.u16 [%0], %1;" :: "r"(ad),     "h"(hb));
                asm volatile("st.shared.u16 [%0], %1;" :: "r"(ad + 2), "h"(lb));
                asm volatile("st.shared.u16 [%0], %1;" :: "r"(ad + 4), "h"(hb));
            }
        }
        __syncwarp();

#pragma unroll
        for (int ks2 = 0; ks2 < 6; ks2++) {
            uint32_t A[4];
            uint32_t aaddr = sP + (uint32_t)((wm * 16 + lrow + ((grp & 1) << 3)) * SP_STR
                                             + (wn * 96 + ks2 * 16 + ((grp >> 1) << 3)) * 2);
            LDSM_X4(A[0], A[1], A[2], A[3], aaddr);
#pragma unroll
            for (int ntp = 0; ntp < 8; ntp++) {
                uint32_t b0, b1, b2, b3;
                uint32_t baddr = sV + (uint32_t)((wn * 96 + ks2 * 16 + lrow + ((grp & 1) << 3)) * SV_STR
                                                 + (ntp * 16 + ((grp >> 1) << 3)) * 2);
                LDSM_X4_T(b0, b1, b2, b3, baddr);
                MMA_BF16(Oc[2 * ntp],     A, b0, b1);
                MMA_BF16(Oc[2 * ntp + 1], A, b2, b3);
            }
        }

        __syncthreads();
        if (kt < qi) load_v((kt + 1) * 64);
    }

    __syncthreads();
    if (wn == 1) {
#pragma unroll
        for (int nt = 0; nt < 16; nt++) {
            int col = nt * 8 + 2 * (lane & 3);
            *(float2*)&mergeO[ra * 128 + col]       = make_float2(Oc[nt][0], Oc[nt][1]);
            *(float2*)&mergeO[(ra + 8) * 128 + col] = make_float2(Oc[nt][2], Oc[nt][3]);
        }
        if ((lane & 3) == 0) {
            mergeM[ra] = m0;     mergeM[ra + 8] = m1;
            mergeL[ra] = l0;     mergeL[ra + 8] = l1;
        }
    }
    __syncthreads();
    if (wn == 0) {
        float M1a = mergeM[ra],     L1a = mergeL[ra];
        float M1b = mergeM[ra + 8], L1b = mergeL[ra + 8];
        float Ma = fmaxf(m0, M1a);
        float w0a = __expf(m0 - Ma), w1a = __expf(M1a - Ma);
        float inva = 1.0f / (l0 * w0a + L1a * w1a);
        float Mb = fmaxf(m1, M1b);
        float w0b = __expf(m1 - Mb), w1b = __expf(M1b - Mb);
        float invb = 1.0f / (l1 * w0b + L1b * w1b);

        size_t obase = ((size_t)(b * SEQ + q0)) * DIM + h * HD;
#pragma unroll
        for (int nt = 0; nt < 16; nt++) {
            int col = nt * 8 + 2 * (lane & 3);
            float2 o1a = *(float2*)&mergeO[ra * 128 + col];
            float2 o1b = *(float2*)&mergeO[(ra + 8) * 128 + col];
            float2 oa = make_float2((Oc[nt][0] * w0a + o1a.x * w1a) * inva,
                                    (Oc[nt][1] * w0a + o1a.y * w1a) * inva);
            float2 ob = make_float2((Oc[nt][2] * w0b + o1b.x * w1b) * invb,
                                    (Oc[nt][3] * w0b + o1b.y * w1b) * invb);
            *(float2*)&Oout[obase + (size_t)ra * DIM + col]       = oa;
            *(float2*)&Oout[obase + (size_t)(ra + 8) * DIM + col] = ob;
        }
    }
}

// ---------------------------------------------------------------------------
extern "C" void kernel_launch(void* const* d_in, const int* in_sizes, int n_in,
                              void* d_out, int out_size)
{
    const float* x  = (const float*)d_in[0];
    const float* wq = (const float*)d_in[1];
    const float* wk = (const float*)d_in[2];
    const float* wv = (const float*)d_in[3];
    const float* wo = (const float*)d_in[4];
    const float* fc = (const float*)d_in[5];
    const float* fs = (const float*)d_in[6];
    float* out = (float*)d_out;

    float *qp, *kp, *vp, *ap;
    __half *xs, *as, *wqs, *wks, *wvs, *wos;
    uint16_t *qs2, *ks2, *vs2;
    cudaGetSymbolAddress((void**)&qp, g_q);
    cudaGetSymbolAddress((void**)&kp, g_k);
    cudaGetSymbolAddress((void**)&vp, g_v);
    cudaGetSymbolAddress((void**)&ap, g_attn);
    cudaGetSymbolAddress((void**)&xs, g_xs);
    cudaGetSymbolAddress((void**)&as, g_as);
    cudaGetSymbolAddress((void**)&wqs, g_wqs);
    cudaGetSymbolAddress((void**)&wks, g_wks);
    cudaGetSymbolAddress((void**)&wvs, g_wvs);
    cudaGetSymbolAddress((void**)&wos, g_wos);
    cudaGetSymbolAddress((void**)&qs2, g_qs2);
    cudaGetSymbolAddress((void**)&ks2, g_ks2);
    cudaGetSymbolAddress((void**)&vs2, g_vs2);

    cudaFuncSetAttribute(gemm_hmma, cudaFuncAttributeMaxDynamicSharedMemorySize, GSMEM);
    cudaFuncSetAttribute(attn_mma, cudaFuncAttributeMaxDynamicSharedMemorySize, ATT_SMEM);

    // Operand conversion (interleaved fp16)
    split_a2<<<(MROWS * KDIM / 8) / 256, 256>>>(x,  xs);
    cvt_b2 <<<(DIM   * KDIM / 8) / 256, 256>>>(wq, wqs);
    cvt_b2 <<<(KVDIM * KDIM / 8) / 256, 256>>>(wk, wks);
    cvt_b2 <<<(KVDIM * KDIM / 8) / 256, 256>>>(wv, wvs);
    cvt_b2 <<<(DIM   * KDIM / 8) / 256, 256>>>(wo, wos);

    // QKV projections (fp16 HMMA, R9 skeleton)
    gemm_hmma<<<dim3(DIM   / 128, MROWS / 128), 256, GSMEM>>>(xs, wqs, qp, MROWS, DIM);
    gemm_hmma<<<dim3(KVDIM / 128, MROWS / 128), 256, GSMEM>>>(xs, wks, kp, MROWS, KVDIM);
    gemm_hmma<<<dim3(KVDIM / 128, MROWS / 128), 256, GSMEM>>>(xs, wvs, vp, MROWS, KVDIM);

    // RoPE + split for attention operands
    rope_split<1><<<(BATCH * NH  * SEQ * 16) / 256, 256>>>(qp, qs2, fc, fs);
    rope_split<0><<<(BATCH * NKV * SEQ * 16) / 256, 256>>>(kp, ks2, fc, fs);
    split_v_kernel<<<(BATCH * NKV * SEQ * 16) / 256, 256>>>(vp, vs2);

    // HMMA flash attention (bf16 3-term, K/V prefetch)
    attn_mma<<<dim3(SEQ / 64, BATCH * NH), 256, ATT_SMEM>>>(qs2, ks2, vs2, ap);

    // Output projection
    split_a2<<<(MROWS * KDIM / 8) / 256, 256>>>(ap, as);
    gemm_hmma<<<dim3(DIM / 128, MROWS / 128), 256, GSMEM>>>(as, wos, out, MROWS, DIM);
}

// round 13
// speedup vs baseline: 2.0565x; 1.4837x over previous
#include <cuda_runtime.h>
#include <cuda_fp16.h>
#include <cuda_bf16.h>
#include <math.h>
#include <stdint.h>

#define BATCH 2
#define SEQ   2048
#define DIM   4096
#define NH    32
#define NKV   8
#define HD    128
#define MROWS 4096   // BATCH*SEQ
#define KVDIM 1024   // NKV*HD
#define KDIM  4096   // GEMM inner K (plain fp16, no interleave)

// ---------------- scratch (zero-init .bss, no runtime allocation) ----------
__device__ float g_q[(size_t)MROWS * DIM];
__device__ float g_k[(size_t)MROWS * KVDIM];
__device__ float g_v[(size_t)MROWS * KVDIM];
__device__ float g_attn[(size_t)MROWS * DIM];

// plain fp16 GEMM operands
__device__ __half g_xs [(size_t)MROWS * KDIM];
__device__ __half g_as [(size_t)MROWS * KDIM];
__device__ __half g_wqs[(size_t)DIM   * KDIM];
__device__ __half g_wks[(size_t)KVDIM * KDIM];
__device__ __half g_wvs[(size_t)KVDIM * KDIM];
__device__ __half g_wos[(size_t)DIM   * KDIM];

// attention split operands (bf16 3-term, proven)
__device__ uint16_t g_qs2[(size_t)BATCH * NH  * SEQ * 384];
__device__ uint16_t g_ks2[(size_t)BATCH * NKV * SEQ * 384];
__device__ uint16_t g_vs2[(size_t)BATCH * NKV * (3*SEQ) * HD];

// ---------------- helpers ---------------------------------------------------
__device__ __forceinline__ uint32_t smem_u32(const void* p) {
    return (uint32_t)__cvta_generic_to_shared(p);
}
__device__ __forceinline__ void cp_async16(uint32_t dst, const void* src) {
    asm volatile("cp.async.cg.shared.global [%0], [%1], 16;" :: "r"(dst), "l"(src) : "memory");
}
__device__ __forceinline__ void cp_commit() {
    asm volatile("cp.async.commit_group;" ::: "memory");
}

#define LDSM_X4(r0, r1, r2, r3, addr) \
    asm volatile("ldmatrix.sync.aligned.m8n8.x4.shared.b16 {%0,%1,%2,%3}, [%4];" \
                 : "=r"(r0), "=r"(r1), "=r"(r2), "=r"(r3) : "r"(addr))

#define LDSM_X4_T(r0, r1, r2, r3, addr) \
    asm volatile("ldmatrix.sync.aligned.m8n8.x4.trans.shared.b16 {%0,%1,%2,%3}, [%4];" \
                 : "=r"(r0), "=r"(r1), "=r"(r2), "=r"(r3) : "r"(addr))

#define MMA_BF16(d, a, b0v, b1v) \
    asm volatile("mma.sync.aligned.m16n8k16.row.col.f32.bf16.bf16.f32 " \
                 "{%0,%1,%2,%3}, {%4,%5,%6,%7}, {%8,%9}, {%0,%1,%2,%3};" \
                 : "+f"((d)[0]), "+f"((d)[1]), "+f"((d)[2]), "+f"((d)[3]) \
                 : "r"((a)[0]), "r"((a)[1]), "r"((a)[2]), "r"((a)[3]), \
                   "r"(b0v), "r"(b1v))

#define MMA_F16(d, a, b0v, b1v) \
    asm volatile("mma.sync.aligned.m16n8k16.row.col.f32.f16.f16.f32 " \
                 "{%0,%1,%2,%3}, {%4,%5,%6,%7}, {%8,%9}, {%0,%1,%2,%3};" \
                 : "+f"((d)[0]), "+f"((d)[1]), "+f"((d)[2]), "+f"((d)[3]) \
                 : "r"((a)[0]), "r"((a)[1]), "r"((a)[2]), "r"((a)[3]), \
                   "r"(b0v), "r"(b1v))

__device__ __forceinline__ void split2(float f, uint16_t& hb, uint16_t& lb) {
    __nv_bfloat16 hi = __float2bfloat16_rn(f);
    __nv_bfloat16 lo = __float2bfloat16_rn(f - __bfloat162float(hi));
    hb = __bfloat16_as_ushort(hi);
    lb = __bfloat16_as_ushort(lo);
}

// ---------------------------------------------------------------------------
// fp32 -> fp16, coalesced
// ---------------------------------------------------------------------------
__global__ void __launch_bounds__(256) cvt_f16(
    const float* __restrict__ src, __half* __restrict__ dst)
{
    size_t t = (size_t)blockIdx.x * 256 + threadIdx.x;
    float4 v0 = *(const float4*)&src[t * 8];
    float4 v1 = *(const float4*)&src[t * 8 + 4];
    float f[8] = {v0.x, v0.y, v0.z, v0.w, v1.x, v1.y, v1.z, v1.w};
    __align__(16) __half h[8];
#pragma unroll
    for (int j = 0; j < 8; j++) h[j] = __float2half_rn(f[j]);
    *(uint4*)&dst[t * 8] = *(uint4*)h;
}

// ---------------------------------------------------------------------------
// fp16 HMMA GEMM — R11 skeleton, K = 4096 plain (no interleave).
// 128x128 CTA, warp 32x64, 4-stage, 80B rows, 2 CTAs/SM.
// ---------------------------------------------------------------------------
#define BKC         32
#define ROW_BYTES   80
#define STAGE_BYTES (256 * ROW_BYTES)
#define NSTAGE      4
#define GSMEM       (NSTAGE * STAGE_BYTES)
#define NITER       (KDIM / BKC)          // 128

__global__ void __launch_bounds__(256) gemm_hmma(
    const __half* __restrict__ A, const __half* __restrict__ Bm,
    float* __restrict__ C, int M, int N)
{
    extern __shared__ __align__(1024) char smem[];
    const uint32_t sbase = smem_u32(smem);

    const int bm = blockIdx.y * 128;
    const int bn = blockIdx.x * 128;
    const int tid = threadIdx.x;
    const int wid = tid >> 5;
    const int lane = tid & 31;
    const int wm = wid & 3;
    const int wn = wid >> 2;

    const __half* ga0 = A  + (size_t)bm * KDIM;
    const __half* gb0 = Bm + (size_t)bn * KDIM;

    const int lc = tid & 3;
    const int lr = tid >> 2;

    auto load_stage = [&](int s, int chunk) {
        const uint32_t sa = sbase + (uint32_t)s * STAGE_BYTES;
        const size_t koff = (size_t)chunk * BKC + lc * 8;
#pragma unroll
        for (int j = 0; j < 4; j++) {
            int r = lr + j * 64;
            const __half* src = (r < 128)
                ? ga0 + (size_t)r * KDIM + koff
                : gb0 + (size_t)(r - 128) * KDIM + koff;
            cp_async16(sa + (uint32_t)(r * ROW_BYTES + lc * 16), src);
        }
        cp_commit();
    };

    float d[2][8][4];
#pragma unroll
    for (int mi = 0; mi < 2; mi++)
#pragma unroll
        for (int nj = 0; nj < 8; nj++)
#pragma unroll
            for (int q = 0; q < 4; q++) d[mi][nj][q] = 0.0f;

    const int grp  = lane >> 3;
    const int lrow = lane & 7;
    const int a_r = lrow + ((grp & 1) << 3);
    const int a_c = (grp >> 1) << 3;
    const int b_r = lrow + ((grp >> 1) << 3);
    const int b_c = (grp & 1) << 3;

    load_stage(0, 0);
    load_stage(1, 1);
    load_stage(2, 2);

    for (int i = 0; i < NITER; i++) {
        const int s = i & (NSTAGE - 1);
        asm volatile("cp.async.wait_group %0;" :: "n"(NSTAGE - 2) : "memory");
        __syncthreads();
        if (i + 3 < NITER) load_stage((i + 3) & (NSTAGE - 1), i + 3);
        else cp_commit();

        const uint32_t aB = sbase + (uint32_t)s * STAGE_BYTES;
        const uint32_t bB = aB + 128 * ROW_BYTES;
#pragma unroll
        for (int step = 0; step < 2; step++) {
            uint32_t af[2][4];
#pragma unroll
            for (int mi = 0; mi < 2; mi++) {
                uint32_t addr = aB + (uint32_t)((wm * 32 + mi * 16 + a_r) * ROW_BYTES
                                                + (step * 16 + a_c) * 2);
                LDSM_X4(af[mi][0], af[mi][1], af[mi][2], af[mi][3], addr);
            }
#pragma unroll
            for (int njp = 0; njp < 4; njp++) {
                uint32_t b0, b1, b2, b3;
                uint32_t addr = bB + (uint32_t)((wn * 64 + njp * 16 + b_r) * ROW_BYTES
                                                + (step * 16 + b_c) * 2);
                LDSM_X4(b0, b1, b2, b3, addr);
#pragma unroll
                for (int mi = 0; mi < 2; mi++) {
                    MMA_F16(d[mi][2 * njp],     af[mi], b0, b1);
                    MMA_F16(d[mi][2 * njp + 1], af[mi], b2, b3);
                }
            }
        }
    }

    const int er = lane >> 2;
    const int ec = (lane & 3) * 2;
#pragma unroll
    for (int mi = 0; mi < 2; mi++) {
#pragma unroll
        for (int nj = 0; nj < 8; nj++) {
            int r0 = bm + wm * 32 + mi * 16 + er;
            int c0 = bn + wn * 64 + nj * 8 + ec;
            *(float2*)&C[(size_t)r0 * N + c0]       = make_float2(d[mi][nj][0], d[mi][nj][1]);
            *(float2*)&C[(size_t)(r0 + 8) * N + c0] = make_float2(d[mi][nj][2], d[mi][nj][3]);
        }
    }
}

// ---------------------------------------------------------------------------
// RoPE + split for Q/K (proven)
// ---------------------------------------------------------------------------
template <int ISQ>
__global__ void rope_split(const float* __restrict__ src, uint16_t* __restrict__ dst,
                           const float* __restrict__ fc, const float* __restrict__ fs)
{
    const int HEADS = ISQ ? NH : NKV;
    int gid = blockIdx.x * blockDim.x + threadIdx.x;
    int part = gid & 15;
    int row  = gid >> 4;
    int s = row & (SEQ - 1);
    int bh = row >> 11;
    int h = bh % HEADS;
    int b = bh / HEADS;
    const float scale = ISQ ? 0.08838834764831845f : 1.0f;

    const float* in = src + ((size_t)(b * SEQ + s)) * (HEADS * HD) + h * HD + part * 8;
    float vals[8];
    *(float4*)&vals[0] = *(const float4*)&in[0];
    *(float4*)&vals[4] = *(const float4*)&in[4];

    __align__(16) uint16_t o[24];
#pragma unroll
    for (int p = 0; p < 4; p++) {
        int i = part * 4 + p;
        float c  = fc[s * 64 + i];
        float sn = fs[s * 64 + i];
        float xr = vals[2 * p], xi = vals[2 * p + 1];
        float rr = (xr * c - xi * sn) * scale;
        float ri = (xr * sn + xi * c) * scale;
        float f2[2] = {rr, ri};
#pragma unroll
        for (int e = 0; e < 2; e++) {
            uint16_t hb, lb;
            split2(f2[e], hb, lb);
            int j = p * 2 + e;
            if (ISQ) { o[3*j] = hb; o[3*j+1] = lb; o[3*j+2] = hb; }
            else     { o[3*j] = hb; o[3*j+1] = hb; o[3*j+2] = lb; }
        }
    }
    uint4* dp = (uint4*)(dst + (size_t)row * 384 + part * 24);
    dp[0] = *(uint4*)&o[0];
    dp[1] = *(uint4*)&o[8];
    dp[2] = *(uint4*)&o[16];
}

__global__ void split_v_kernel(const float* __restrict__ src, uint16_t* __restrict__ dst)
{
    int gid = blockIdx.x * blockDim.x + threadIdx.x;
    int part = gid & 15;
    int row  = gid >> 4;
    int t = row & (SEQ - 1);
    int bkv = row >> 11;
    int kv = bkv & (NKV - 1);
    int b = bkv >> 3;

    const float* in = src + ((size_t)(b * SEQ + t)) * KVDIM + kv * HD + part * 8;
    float vals[8];
    *(float4*)&vals[0] = *(const float4*)&in[0];
    *(float4*)&vals[4] = *(const float4*)&in[4];

    __align__(16) uint16_t hi8[8], lo8[8];
#pragma unroll
    for (int j = 0; j < 8; j++) {
        uint16_t hb, lb;
        split2(vals[j], hb, lb);
        hi8[j] = hb; lo8[j] = lb;
    }
    uint16_t* out = dst + ((size_t)bkv * (3 * SEQ) + 3 * t) * HD + part * 8;
    *(uint4*)&out[0]        = *(uint4*)&hi8[0];
    *(uint4*)&out[HD]       = *(uint4*)&hi8[0];
    *(uint4*)&out[2 * HD]   = *(uint4*)&lo8[0];
}

// ---------------------------------------------------------------------------
// HMMA causal flash attention (R9, proven: bf16 3-term + K/V prefetch)
// ---------------------------------------------------------------------------
#define SQ_STR   784
#define SK_STR   784
#define SV_STR   272
#define SP_STR   400
#define SQ_OFF   0
#define SK_OFF   50176
#define SV_OFF   100352
#define SP_OFF   152576
#define ATT_SMEM 178176

__global__ void __launch_bounds__(256) attn_mma(
    const uint16_t* __restrict__ Qs, const uint16_t* __restrict__ Ks,
    const uint16_t* __restrict__ Vs, float* __restrict__ Oout)
{
    extern __shared__ __align__(1024) char smem[];
    const uint32_t sQ = smem_u32(smem) + SQ_OFF;
    const uint32_t sK = smem_u32(smem) + SK_OFF;
    const uint32_t sV = smem_u32(smem) + SV_OFF;
    const uint32_t sP = smem_u32(smem) + SP_OFF;
    float* mergeO = (float*)smem;
    float* mergeM = (float*)(smem + 32768);
    float* mergeL = (float*)(smem + 32768 + 256);

    const int qi = (SEQ / 64 - 1) - blockIdx.x;
    const int bh = blockIdx.y;
    const int b = bh >> 5, h = bh & 31, kvh = h >> 2;
    const int q0 = qi * 64;
    const int tid = threadIdx.x;
    const int wid = tid >> 5, lane = tid & 31;
    const int wm = wid & 3, wn = wid >> 2;
    const int grp = lane >> 3, lrow = lane & 7;

    const uint16_t* gk = Ks + ((size_t)(b * NKV + kvh) * SEQ) * 384;
    const uint16_t* gv = Vs + ((size_t)(b * NKV + kvh) * (3 * SEQ)) * HD;

    auto load_k = [&](int t0) {
#pragma unroll
        for (int j = 0; j < 12; j++) {
            int id = tid + j * 256;
            int r = id / 48, c = id % 48;
            cp_async16(sK + (uint32_t)(r * SK_STR + c * 16),
                       gk + ((size_t)(t0 + r)) * 384 + c * 8);
        }
        cp_commit();
    };
    auto load_v = [&](int t0) {
#pragma unroll
        for (int j = 0; j < 12; j++) {
            int id = tid + j * 256;
            int r = id / 16, c = id % 16;
            cp_async16(sV + (uint32_t)(r * SV_STR + c * 16),
                       gv + ((size_t)(t0 * 3 + r)) * HD + c * 8);
        }
        cp_commit();
    };

    const uint16_t* gq = Qs + ((size_t)(b * NH + h) * SEQ + q0) * 384;
#pragma unroll
    for (int j = 0; j < 12; j++) {
        int id = tid + j * 256;
        int r = id / 48, c = id % 48;
        cp_async16(sQ + (uint32_t)(r * SQ_STR + c * 16), gq + (size_t)r * 384 + c * 8);
    }
    cp_commit();
    load_k(0);
    load_v(0);

    float m0 = -1e30f, m1 = -1e30f, l0 = 0.0f, l1 = 0.0f;
    float Oc[16][4];
#pragma unroll
    for (int j = 0; j < 16; j++)
#pragma unroll
        for (int q = 0; q < 4; q++) Oc[j][q] = 0.0f;

    const int ra = wm * 16 + (lane >> 2);

    for (int kt = 0; kt <= qi; kt++) {
        asm volatile("cp.async.wait_group 0;" ::: "memory");
        __syncthreads();

        float Sa[4][4];
#pragma unroll
        for (int nt = 0; nt < 4; nt++)
#pragma unroll
            for (int q = 0; q < 4; q++) Sa[nt][q] = 0.0f;

#pragma unroll
        for (int ks = 0; ks < 24; ks++) {
            uint32_t A[4];
            uint32_t aaddr = sQ + (uint32_t)((wm * 16 + lrow + ((grp & 1) << 3)) * SQ_STR
                                             + (ks * 16 + ((grp >> 1) << 3)) * 2);
            LDSM_X4(A[0], A[1], A[2], A[3], aaddr);
#pragma unroll
            for (int ntp = 0; ntp < 2; ntp++) {
                uint32_t b0, b1, b2, b3;
                uint32_t baddr = sK + (uint32_t)((wn * 32 + ntp * 16 + lrow + ((grp >> 1) << 3)) * SK_STR
                                                 + (ks * 16 + ((grp & 1) << 3)) * 2);
                LDSM_X4(b0, b1, b2, b3, baddr);
                MMA_BF16(Sa[2 * ntp],     A, b0, b1);
                MMA_BF16(Sa[2 * ntp + 1], A, b2, b3);
            }
        }

        __syncthreads();
        if (kt < qi) load_k((kt + 1) * 64);

        if (kt == qi) {
#pragma unroll
            for (int nt = 0; nt < 4; nt++) {
                int tb = wn * 32 + nt * 8 + 2 * (lane & 3);
                if (tb     > ra)     Sa[nt][0] = -1e30f;
                if (tb + 1 > ra)     Sa[nt][1] = -1e30f;
                if (tb     > ra + 8) Sa[nt][2] = -1e30f;
                if (tb + 1 > ra + 8) Sa[nt][3] = -1e30f;
            }
        }

        float hm0 = -1e30f, hm1 = -1e30f;
#pragma unroll
        for (int nt = 0; nt < 4; nt++) {
            hm0 = fmaxf(hm0, fmaxf(Sa[nt][0], Sa[nt][1]));
            hm1 = fmaxf(hm1, fmaxf(Sa[nt][2], Sa[nt][3]));
        }
        hm0 = fmaxf(hm0, __shfl_xor_sync(0xffffffffu, hm0, 1));
        hm0 = fmaxf(hm0, __shfl_xor_sync(0xffffffffu, hm0, 2));
        hm1 = fmaxf(hm1, __shfl_xor_sync(0xffffffffu, hm1, 1));
        hm1 = fmaxf(hm1, __shfl_xor_sync(0xffffffffu, hm1, 2));

        float mn0 = fmaxf(m0, hm0), mn1 = fmaxf(m1, hm1);
        float al0 = __expf(m0 - mn0), al1 = __expf(m1 - mn1);
        m0 = mn0; m1 = mn1;

        float hs0 = 0.0f, hs1 = 0.0f;
#pragma unroll
        for (int nt = 0; nt < 4; nt++) {
            Sa[nt][0] = __expf(Sa[nt][0] - mn0); hs0 += Sa[nt][0];
            Sa[nt][1] = __expf(Sa[nt][1] - mn0); hs0 += Sa[nt][1];
            Sa[nt][2] = __expf(Sa[nt][2] - mn1); hs1 += Sa[nt][2];
            Sa[nt][3] = __expf(Sa[nt][3] - mn1); hs1 += Sa[nt][3];
        }
        hs0 += __shfl_xor_sync(0xffffffffu, hs0, 1);
        hs0 += __shfl_xor_sync(0xffffffffu, hs0, 2);
        hs1 += __shfl_xor_sync(0xffffffffu, hs1, 1);
        hs1 += __shfl_xor_sync(0xffffffffu, hs1, 2);
        l0 = l0 * al0 + hs0;
        l1 = l1 * al1 + hs1;
#pragma unroll
        for (int j = 0; j < 16; j++) {
            Oc[j][0] *= al0; Oc[j][1] *= al0;
            Oc[j][2] *= al1; Oc[j][3] *= al1;
        }

        __syncwarp();
#pragma unroll
        for (int nt = 0; nt < 4; nt++) {
            int tl0 = wn * 32 + nt * 8 + 2 * (lane & 3);
#pragma unroll
            for (int q = 0; q < 4; q++) {
                int row = ra + ((q >> 1) << 3);
                int t = tl0 + (q & 1);
                float p = Sa[nt][q];
                uint16_t hb, lb;
                split2(p, hb, lb);
                uint32_t ad = sP + (uint32_t)(row * SP_STR + t * 6);
                asm volatile("st.shared.u16 [%0], %1;" :: "r"(ad),     "h"(hb));
                asm volatile("st.shared.u16 [%0], %1;" :: "r"(ad + 2), "h"(lb));
                asm volatile("st.shared.u16 [%0], %1;" :: "r"(ad + 4), "h"(hb));
            }
        }
        __syncwarp();

#pragma unroll
        for (int ks2 = 0; ks2 < 6; ks2++) {
            uint32_t A[4];
            uint32_t aaddr = sP + (uint32_t)((wm * 16 + lrow + ((grp & 1) << 3)) * SP_STR
                                             + (wn * 96 + ks2 * 16 + ((grp >> 1) << 3)) * 2);
            LDSM_X4(A[0], A[1], A[2], A[3], aaddr);
#pragma unroll
            for (int ntp = 0; ntp < 8; ntp++) {
                uint32_t b0, b1, b2, b3;
                uint32_t baddr = sV + (uint32_t)((wn * 96 + ks2 * 16 + lrow + ((grp & 1) << 3)) * SV_STR
                                                 + (ntp * 16 + ((grp >> 1) << 3)) * 2);
                LDSM_X4_T(b0, b1, b2, b3, baddr);
                MMA_BF16(Oc[2 * ntp],     A, b0, b1);
                MMA_BF16(Oc[2 * ntp + 1], A, b2, b3);
            }
        }

        __syncthreads();
        if (kt < qi) load_v((kt + 1) * 64);
    }

    __syncthreads();
    if (wn == 1) {
#pragma unroll
        for (int nt = 0; nt < 16; nt++) {
            int col = nt * 8 + 2 * (lane & 3);
            *(float2*)&mergeO[ra * 128 + col]       = make_float2(Oc[nt][0], Oc[nt][1]);
            *(float2*)&mergeO[(ra + 8) * 128 + col] = make_float2(Oc[nt][2], Oc[nt][3]);
        }
        if ((lane & 3) == 0) {
            mergeM[ra] = m0;     mergeM[ra + 8] = m1;
            mergeL[ra] = l0;     mergeL[ra + 8] = l1;
        }
    }
    __syncthreads();
    if (wn == 0) {
        float M1a = mergeM[ra],     L1a = mergeL[ra];
        float M1b = mergeM[ra + 8], L1b = mergeL[ra + 8];
        float Ma = fmaxf(m0, M1a);
        float w0a = __expf(m0 - Ma), w1a = __expf(M1a - Ma);
        float inva = 1.0f / (l0 * w0a + L1a * w1a);
        float Mb = fmaxf(m1, M1b);
        float w0b = __expf(m1 - Mb), w1b = __expf(M1b - Mb);
        float invb = 1.0f / (l1 * w0b + L1b * w1b);

        size_t obase = ((size_t)(b * SEQ + q0)) * DIM + h * HD;
#pragma unroll
        for (int nt = 0; nt < 16; nt++) {
            int col = nt * 8 + 2 * (lane & 3);
            float2 o1a = *(float2*)&mergeO[ra * 128 + col];
            float2 o1b = *(float2*)&mergeO[(ra + 8) * 128 + col];
            float2 oa = make_float2((Oc[nt][0] * w0a + o1a.x * w1a) * inva,
                                    (Oc[nt][1] * w0a + o1a.y * w1a) * inva);
            float2 ob = make_float2((Oc[nt][2] * w0b + o1b.x * w1b) * invb,
                                    (Oc[nt][3] * w0b + o1b.y * w1b) * invb);
            *(float2*)&Oout[obase + (size_t)ra * DIM + col]       = oa;
            *(float2*)&Oout[obase + (size_t)(ra + 8) * DIM + col] = ob;
        }
    }
}

// ---------------------------------------------------------------------------
extern "C" void kernel_launch(void* const* d_in, const int* in_sizes, int n_in,
                              void* d_out, int out_size)
{
    const float* x  = (const float*)d_in[0];
    const float* wq = (const float*)d_in[1];
    const float* wk = (const float*)d_in[2];
    const float* wv = (const float*)d_in[3];
    const float* wo = (const float*)d_in[4];
    const float* fc = (const float*)d_in[5];
    const float* fs = (const float*)d_in[6];
    float* out = (float*)d_out;

    float *qp, *kp, *vp, *ap;
    __half *xs, *as, *wqs, *wks, *wvs, *wos;
    uint16_t *qs2, *ks2, *vs2;
    cudaGetSymbolAddress((void**)&qp, g_q);
    cudaGetSymbolAddress((void**)&kp, g_k);
    cudaGetSymbolAddress((void**)&vp, g_v);
    cudaGetSymbolAddress((void**)&ap, g_attn);
    cudaGetSymbolAddress((void**)&xs, g_xs);
    cudaGetSymbolAddress((void**)&as, g_as);
    cudaGetSymbolAddress((void**)&wqs, g_wqs);
    cudaGetSymbolAddress((void**)&wks, g_wks);
    cudaGetSymbolAddress((void**)&wvs, g_wvs);
    cudaGetSymbolAddress((void**)&wos, g_wos);
    cudaGetSymbolAddress((void**)&qs2, g_qs2);
    cudaGetSymbolAddress((void**)&ks2, g_ks2);
    cudaGetSymbolAddress((void**)&vs2, g_vs2);

    cudaFuncSetAttribute(gemm_hmma, cudaFuncAttributeMaxDynamicSharedMemorySize, GSMEM);
    cudaFuncSetAttribute(attn_mma, cudaFuncAttributeMaxDynamicSharedMemorySize, ATT_SMEM);

    // fp16 conversion (single rounding each side)
    cvt_f16<<<(MROWS * KDIM / 8) / 256, 256>>>(x,  xs);
    cvt_f16<<<(DIM   * KDIM / 8) / 256, 256>>>(wq, wqs);
    cvt_f16<<<(KVDIM * KDIM / 8) / 256, 256>>>(wk, wks);
    cvt_f16<<<(KVDIM * KDIM / 8) / 256, 256>>>(wv, wvs);
    cvt_f16<<<(DIM   * KDIM / 8) / 256, 256>>>(wo, wos);

    // QKV projections (plain fp16 HMMA)
    gemm_hmma<<<dim3(DIM   / 128, MROWS / 128), 256, GSMEM>>>(xs, wqs, qp, MROWS, DIM);
    gemm_hmma<<<dim3(KVDIM / 128, MROWS / 128), 256, GSMEM>>>(xs, wks, kp, MROWS, KVDIM);
    gemm_hmma<<<dim3(KVDIM / 128, MROWS / 128), 256, GSMEM>>>(xs, wvs, vp, MROWS, KVDIM);

    // RoPE + split for attention operands
    rope_split<1><<<(BATCH * NH  * SEQ * 16) / 256, 256>>>(qp, qs2, fc, fs);
    rope_split<0><<<(BATCH * NKV * SEQ * 16) / 256, 256>>>(kp, ks2, fc, fs);
    split_v_kernel<<<(BATCH * NKV * SEQ * 16) / 256, 256>>>(vp, vs2);

    // HMMA flash attention (bf16 3-term, K/V prefetch)
    attn_mma<<<dim3(SEQ / 64, BATCH * NH), 256, ATT_SMEM>>>(qs2, ks2, vs2, ap);

    // Output projection
    cvt_f16<<<(MROWS * KDIM / 8) / 256, 256>>>(ap, as);
    gemm_hmma<<<dim3(DIM / 128, MROWS / 128), 256, GSMEM>>>(as, wos, out, MROWS, DIM);
}

// round 14
// speedup vs baseline: 2.7248x; 1.3250x over previous
#include <cuda_runtime.h>
#include <cuda_fp16.h>
#include <math.h>
#include <stdint.h>

#define BATCH 2
#define SEQ   2048
#define DIM   4096
#define NH    32
#define NKV   8
#define HD    128
#define MROWS 4096   // BATCH*SEQ
#define KVDIM 1024   // NKV*HD
#define KDIM  4096   // GEMM inner K

// ---------------- scratch (zero-init .bss, no runtime allocation) ----------
__device__ float g_q[(size_t)MROWS * DIM];
__device__ float g_k[(size_t)MROWS * KVDIM];
__device__ float g_v[(size_t)MROWS * KVDIM];
__device__ float g_attn[(size_t)MROWS * DIM];

// plain fp16 GEMM operands
__device__ __half g_xs [(size_t)MROWS * KDIM];
__device__ __half g_as [(size_t)MROWS * KDIM];
__device__ __half g_wqs[(size_t)DIM   * KDIM];
__device__ __half g_wks[(size_t)KVDIM * KDIM];
__device__ __half g_wvs[(size_t)KVDIM * KDIM];
__device__ __half g_wos[(size_t)DIM   * KDIM];

// attention fp16 operands: Q (hi,lo) interleaved K'=256; K (k,k) dup; V plain
__device__ __half g_qs2[(size_t)BATCH * NH  * SEQ * 256];
__device__ __half g_ks2[(size_t)BATCH * NKV * SEQ * 256];
__device__ __half g_vs2[(size_t)BATCH * NKV * SEQ * HD];

// ---------------- helpers ---------------------------------------------------
__device__ __forceinline__ uint32_t smem_u32(const void* p) {
    return (uint32_t)__cvta_generic_to_shared(p);
}
__device__ __forceinline__ void cp_async16(uint32_t dst, const void* src) {
    asm volatile("cp.async.cg.shared.global [%0], [%1], 16;" :: "r"(dst), "l"(src) : "memory");
}
__device__ __forceinline__ void cp_commit() {
    asm volatile("cp.async.commit_group;" ::: "memory");
}

#define LDSM_X4(r0, r1, r2, r3, addr) \
    asm volatile("ldmatrix.sync.aligned.m8n8.x4.shared.b16 {%0,%1,%2,%3}, [%4];" \
                 : "=r"(r0), "=r"(r1), "=r"(r2), "=r"(r3) : "r"(addr))

#define LDSM_X4_T(r0, r1, r2, r3, addr) \
    asm volatile("ldmatrix.sync.aligned.m8n8.x4.trans.shared.b16 {%0,%1,%2,%3}, [%4];" \
                 : "=r"(r0), "=r"(r1), "=r"(r2), "=r"(r3) : "r"(addr))

#define MMA_F16(d, a, b0v, b1v) \
    asm volatile("mma.sync.aligned.m16n8k16.row.col.f32.f16.f16.f32 " \
                 "{%0,%1,%2,%3}, {%4,%5,%6,%7}, {%8,%9}, {%0,%1,%2,%3};" \
                 : "+f"((d)[0]), "+f"((d)[1]), "+f"((d)[2]), "+f"((d)[3]) \
                 : "r"((a)[0]), "r"((a)[1]), "r"((a)[2]), "r"((a)[3]), \
                   "r"(b0v), "r"(b1v))

// ---------------------------------------------------------------------------
// fp32 -> fp16, coalesced
// ---------------------------------------------------------------------------
__global__ void __launch_bounds__(256) cvt_f16(
    const float* __restrict__ src, __half* __restrict__ dst)
{
    size_t t = (size_t)blockIdx.x * 256 + threadIdx.x;
    float4 v0 = *(const float4*)&src[t * 8];
    float4 v1 = *(const float4*)&src[t * 8 + 4];
    float f[8] = {v0.x, v0.y, v0.z, v0.w, v1.x, v1.y, v1.z, v1.w};
    __align__(16) __half h[8];
#pragma unroll
    for (int j = 0; j < 8; j++) h[j] = __float2half_rn(f[j]);
    *(uint4*)&dst[t * 8] = *(uint4*)h;
}

// ---------------------------------------------------------------------------
// fp16 HMMA GEMM (R12, proven): 128x128 CTA, warp 32x64, 4-stage, 80B rows.
// ---------------------------------------------------------------------------
#define BKC         32
#define ROW_BYTES   80
#define STAGE_BYTES (256 * ROW_BYTES)
#define NSTAGE      4
#define GSMEM       (NSTAGE * STAGE_BYTES)
#define NITER       (KDIM / BKC)          // 128

__global__ void __launch_bounds__(256) gemm_hmma(
    const __half* __restrict__ A, const __half* __restrict__ Bm,
    float* __restrict__ C, int M, int N)
{
    extern __shared__ __align__(1024) char smem[];
    const uint32_t sbase = smem_u32(smem);

    const int bm = blockIdx.y * 128;
    const int bn = blockIdx.x * 128;
    const int tid = threadIdx.x;
    const int wid = tid >> 5;
    const int lane = tid & 31;
    const int wm = wid & 3;
    const int wn = wid >> 2;

    const __half* ga0 = A  + (size_t)bm * KDIM;
    const __half* gb0 = Bm + (size_t)bn * KDIM;

    const int lc = tid & 3;
    const int lr = tid >> 2;

    auto load_stage = [&](int s, int chunk) {
        const uint32_t sa = sbase + (uint32_t)s * STAGE_BYTES;
        const size_t koff = (size_t)chunk * BKC + lc * 8;
#pragma unroll
        for (int j = 0; j < 4; j++) {
            int r = lr + j * 64;
            const __half* src = (r < 128)
                ? ga0 + (size_t)r * KDIM + koff
                : gb0 + (size_t)(r - 128) * KDIM + koff;
            cp_async16(sa + (uint32_t)(r * ROW_BYTES + lc * 16), src);
        }
        cp_commit();
    };

    float d[2][8][4];
#pragma unroll
    for (int mi = 0; mi < 2; mi++)
#pragma unroll
        for (int nj = 0; nj < 8; nj++)
#pragma unroll
            for (int q = 0; q < 4; q++) d[mi][nj][q] = 0.0f;

    const int grp  = lane >> 3;
    const int lrow = lane & 7;
    const int a_r = lrow + ((grp & 1) << 3);
    const int a_c = (grp >> 1) << 3;
    const int b_r = lrow + ((grp >> 1) << 3);
    const int b_c = (grp & 1) << 3;

    load_stage(0, 0);
    load_stage(1, 1);
    load_stage(2, 2);

    for (int i = 0; i < NITER; i++) {
        const int s = i & (NSTAGE - 1);
        asm volatile("cp.async.wait_group %0;" :: "n"(NSTAGE - 2) : "memory");
        __syncthreads();
        if (i + 3 < NITER) load_stage((i + 3) & (NSTAGE - 1), i + 3);
        else cp_commit();

        const uint32_t aB = sbase + (uint32_t)s * STAGE_BYTES;
        const uint32_t bB = aB + 128 * ROW_BYTES;
#pragma unroll
        for (int step = 0; step < 2; step++) {
            uint32_t af[2][4];
#pragma unroll
            for (int mi = 0; mi < 2; mi++) {
                uint32_t addr = aB + (uint32_t)((wm * 32 + mi * 16 + a_r) * ROW_BYTES
                                                + (step * 16 + a_c) * 2);
                LDSM_X4(af[mi][0], af[mi][1], af[mi][2], af[mi][3], addr);
            }
#pragma unroll
            for (int njp = 0; njp < 4; njp++) {
                uint32_t b0, b1, b2, b3;
                uint32_t addr = bB + (uint32_t)((wn * 64 + njp * 16 + b_r) * ROW_BYTES
                                                + (step * 16 + b_c) * 2);
                LDSM_X4(b0, b1, b2, b3, addr);
#pragma unroll
                for (int mi = 0; mi < 2; mi++) {
                    MMA_F16(d[mi][2 * njp],     af[mi], b0, b1);
                    MMA_F16(d[mi][2 * njp + 1], af[mi], b2, b3);
                }
            }
        }
    }

    const int er = lane >> 2;
    const int ec = (lane & 3) * 2;
#pragma unroll
    for (int mi = 0; mi < 2; mi++) {
#pragma unroll
        for (int nj = 0; nj < 8; nj++) {
            int r0 = bm + wm * 32 + mi * 16 + er;
            int c0 = bn + wn * 64 + nj * 8 + ec;
            *(float2*)&C[(size_t)r0 * N + c0]       = make_float2(d[mi][nj][0], d[mi][nj][1]);
            *(float2*)&C[(size_t)(r0 + 8) * N + c0] = make_float2(d[mi][nj][2], d[mi][nj][3]);
        }
    }
}

// ---------------------------------------------------------------------------
// RoPE + fp16 pack for Q (hi,lo interleaved, scale folded) / K ((k,k) dup)
// ---------------------------------------------------------------------------
template <int ISQ>
__global__ void rope_pack(const float* __restrict__ src, __half* __restrict__ dst,
                          const float* __restrict__ fc, const float* __restrict__ fs)
{
    const int HEADS = ISQ ? NH : NKV;
    int gid = blockIdx.x * blockDim.x + threadIdx.x;
    int part = gid & 15;
    int row  = gid >> 4;
    int s = row & (SEQ - 1);
    int bh = row >> 11;
    int h = bh % HEADS;
    int b = bh / HEADS;
    const float scale = ISQ ? 0.08838834764831845f : 1.0f;

    const float* in = src + ((size_t)(b * SEQ + s)) * (HEADS * HD) + h * HD + part * 8;
    float vals[8];
    *(float4*)&vals[0] = *(const float4*)&in[0];
    *(float4*)&vals[4] = *(const float4*)&in[4];

    __align__(16) __half o[16];
#pragma unroll
    for (int p = 0; p < 4; p++) {
        int i = part * 4 + p;
        float c  = fc[s * 64 + i];
        float sn = fs[s * 64 + i];
        float xr = vals[2 * p], xi = vals[2 * p + 1];
        float rr = (xr * c - xi * sn) * scale;
        float ri = (xr * sn + xi * c) * scale;
        float f2[2] = {rr, ri};
#pragma unroll
        for (int e = 0; e < 2; e++) {
            int j = p * 2 + e;
            __half hv = __float2half_rn(f2[e]);
            if (ISQ) {
                __half lv = __float2half_rn(f2[e] - __half2float(hv));
                o[2*j] = hv; o[2*j+1] = lv;
            } else {
                o[2*j] = hv; o[2*j+1] = hv;
            }
        }
    }
    uint4* dp = (uint4*)(dst + (size_t)row * 256 + part * 16);
    dp[0] = *(uint4*)&o[0];
    dp[1] = *(uint4*)&o[8];
}

// V: plain fp16 rows [ (b*NKV+kv)*SEQ + t, 128 ]
__global__ void cvt_v_f16(const float* __restrict__ src, __half* __restrict__ dst)
{
    int gid = blockIdx.x * blockDim.x + threadIdx.x;
    int part = gid & 15;
    int row  = gid >> 4;
    int t = row & (SEQ - 1);
    int bkv = row >> 11;
    int kv = bkv & (NKV - 1);
    int b = bkv >> 3;

    const float* in = src + ((size_t)(b * SEQ + t)) * KVDIM + kv * HD + part * 8;
    float vals[8];
    *(float4*)&vals[0] = *(const float4*)&in[0];
    *(float4*)&vals[4] = *(const float4*)&in[4];

    __align__(16) __half h[8];
#pragma unroll
    for (int j = 0; j < 8; j++) h[j] = __float2half_rn(vals[j]);
    *(uint4*)&dst[(size_t)row * HD + part * 8] = *(uint4*)h;
}

// ---------------------------------------------------------------------------
// fp16 causal flash attention: Q (hi,lo)x(k,k) S-chain k=256, fp16 P*V k=64.
// CTA 64q x seq; 8 warps = 4m x 2 t-halves; independent softmax + final merge.
// ---------------------------------------------------------------------------
#define SQ_STR   528
#define SK_STR   528
#define SV_STR   272
#define SP_STR   144
#define SQ_OFF   0
#define SK_OFF   33792
#define SV_OFF   67584
#define SP_OFF   84992
#define ATT_SMEM 94208

__global__ void __launch_bounds__(256) attn_mma(
    const __half* __restrict__ Qs, const __half* __restrict__ Ks,
    const __half* __restrict__ Vs, float* __restrict__ Oout)
{
    extern __shared__ __align__(1024) char smem[];
    const uint32_t sQ = smem_u32(smem) + SQ_OFF;
    const uint32_t sK = smem_u32(smem) + SK_OFF;
    const uint32_t sV = smem_u32(smem) + SV_OFF;
    const uint32_t sP = smem_u32(smem) + SP_OFF;
    float* mergeO = (float*)smem;
    float* mergeM = (float*)(smem + 32768);
    float* mergeL = (float*)(smem + 32768 + 256);

    const int qi = (SEQ / 64 - 1) - blockIdx.x;
    const int bh = blockIdx.y;
    const int b = bh >> 5, h = bh & 31, kvh = h >> 2;
    const int q0 = qi * 64;
    const int tid = threadIdx.x;
    const int wid = tid >> 5, lane = tid & 31;
    const int wm = wid & 3, wn = wid >> 2;
    const int grp = lane >> 3, lrow = lane & 7;

    const __half* gk = Ks + ((size_t)(b * NKV + kvh) * SEQ) * 256;
    const __half* gv = Vs + ((size_t)(b * NKV + kvh) * SEQ) * HD;

    auto load_k = [&](int t0) {
#pragma unroll
        for (int j = 0; j < 8; j++) {
            int id = tid + j * 256;
            int r = id >> 5, c = id & 31;
            cp_async16(sK + (uint32_t)(r * SK_STR + c * 16),
                       gk + ((size_t)(t0 + r)) * 256 + c * 8);
        }
        cp_commit();
    };
    auto load_v = [&](int t0) {
#pragma unroll
        for (int j = 0; j < 4; j++) {
            int id = tid + j * 256;
            int r = id >> 4, c = id & 15;
            cp_async16(sV + (uint32_t)(r * SV_STR + c * 16),
                       gv + ((size_t)(t0 + r)) * HD + c * 8);
        }
        cp_commit();
    };

    const __half* gq = Qs + ((size_t)(b * NH + h) * SEQ + q0) * 256;
#pragma unroll
    for (int j = 0; j < 8; j++) {
        int id = tid + j * 256;
        int r = id >> 5, c = id & 31;
        cp_async16(sQ + (uint32_t)(r * SQ_STR + c * 16), gq + (size_t)r * 256 + c * 8);
    }
    cp_commit();
    load_k(0);
    load_v(0);

    float m0 = -1e30f, m1 = -1e30f, l0 = 0.0f, l1 = 0.0f;
    float Oc[16][4];
#pragma unroll
    for (int j = 0; j < 16; j++)
#pragma unroll
        for (int q = 0; q < 4; q++) Oc[j][q] = 0.0f;

    const int ra = wm * 16 + (lane >> 2);

    for (int kt = 0; kt <= qi; kt++) {
        asm volatile("cp.async.wait_group 0;" ::: "memory");
        __syncthreads();

        // ---- S = Q' K'^T (k = 256) ----
        float Sa[4][4];
#pragma unroll
        for (int nt = 0; nt < 4; nt++)
#pragma unroll
            for (int q = 0; q < 4; q++) Sa[nt][q] = 0.0f;

#pragma unroll
        for (int ks = 0; ks < 16; ks++) {
            uint32_t A[4];
            uint32_t aaddr = sQ + (uint32_t)((wm * 16 + lrow + ((grp & 1) << 3)) * SQ_STR
                                             + (ks * 16 + ((grp >> 1) << 3)) * 2);
            LDSM_X4(A[0], A[1], A[2], A[3], aaddr);
#pragma unroll
            for (int ntp = 0; ntp < 2; ntp++) {
                uint32_t b0, b1, b2, b3;
                uint32_t baddr = sK + (uint32_t)((wn * 32 + ntp * 16 + lrow + ((grp >> 1) << 3)) * SK_STR
                                                 + (ks * 16 + ((grp & 1) << 3)) * 2);
                LDSM_X4(b0, b1, b2, b3, baddr);
                MMA_F16(Sa[2 * ntp],     A, b0, b1);
                MMA_F16(Sa[2 * ntp + 1], A, b2, b3);
            }
        }

        // sK dead -> prefetch next K under softmax + PV
        __syncthreads();
        if (kt < qi) load_k((kt + 1) * 64);

        if (kt == qi) {
#pragma unroll
            for (int nt = 0; nt < 4; nt++) {
                int tb = wn * 32 + nt * 8 + 2 * (lane & 3);
                if (tb     > ra)     Sa[nt][0] = -1e30f;
                if (tb + 1 > ra)     Sa[nt][1] = -1e30f;
                if (tb     > ra + 8) Sa[nt][2] = -1e30f;
                if (tb + 1 > ra + 8) Sa[nt][3] = -1e30f;
            }
        }

        float hm0 = -1e30f, hm1 = -1e30f;
#pragma unroll
        for (int nt = 0; nt < 4; nt++) {
            hm0 = fmaxf(hm0, fmaxf(Sa[nt][0], Sa[nt][1]));
            hm1 = fmaxf(hm1, fmaxf(Sa[nt][2], Sa[nt][3]));
        }
        hm0 = fmaxf(hm0, __shfl_xor_sync(0xffffffffu, hm0, 1));
        hm0 = fmaxf(hm0, __shfl_xor_sync(0xffffffffu, hm0, 2));
        hm1 = fmaxf(hm1, __shfl_xor_sync(0xffffffffu, hm1, 1));
        hm1 = fmaxf(hm1, __shfl_xor_sync(0xffffffffu, hm1, 2));

        float mn0 = fmaxf(m0, hm0), mn1 = fmaxf(m1, hm1);
        float al0 = __expf(m0 - mn0), al1 = __expf(m1 - mn1);
        m0 = mn0; m1 = mn1;

        float hs0 = 0.0f, hs1 = 0.0f;
#pragma unroll
        for (int nt = 0; nt < 4; nt++) {
            Sa[nt][0] = __expf(Sa[nt][0] - mn0); hs0 += Sa[nt][0];
            Sa[nt][1] = __expf(Sa[nt][1] - mn0); hs0 += Sa[nt][1];
            Sa[nt][2] = __expf(Sa[nt][2] - mn1); hs1 += Sa[nt][2];
            Sa[nt][3] = __expf(Sa[nt][3] - mn1); hs1 += Sa[nt][3];
        }
        hs0 += __shfl_xor_sync(0xffffffffu, hs0, 1);
        hs0 += __shfl_xor_sync(0xffffffffu, hs0, 2);
        hs1 += __shfl_xor_sync(0xffffffffu, hs1, 1);
        hs1 += __shfl_xor_sync(0xffffffffu, hs1, 2);
        l0 = l0 * al0 + hs0;
        l1 = l1 * al1 + hs1;
#pragma unroll
        for (int j = 0; j < 16; j++) {
            Oc[j][0] *= al0; Oc[j][1] *= al0;
            Oc[j][2] *= al1; Oc[j][3] *= al1;
        }

        // ---- P -> fp16 in smem ----
        __syncwarp();
#pragma unroll
        for (int nt = 0; nt < 4; nt++) {
            int tl0 = wn * 32 + nt * 8 + 2 * (lane & 3);
#pragma unroll
            for (int q = 0; q < 4; q++) {
                int row = ra + ((q >> 1) << 3);
                int t = tl0 + (q & 1);
                uint16_t pv = __half_as_ushort(__float2half_rn(Sa[nt][q]));
                uint32_t ad = sP + (uint32_t)(row * SP_STR + t * 2);
                asm volatile("st.shared.u16 [%0], %1;" :: "r"(ad), "h"(pv));
            }
        }
        __syncwarp();

        // ---- O += P V (k = 32 per t-half) ----
#pragma unroll
        for (int ks2 = 0; ks2 < 2; ks2++) {
            uint32_t A[4];
            uint32_t aaddr = sP + (uint32_t)((wm * 16 + lrow + ((grp & 1) << 3)) * SP_STR
                                             + (wn * 32 + ks2 * 16 + ((grp >> 1) << 3)) * 2);
            LDSM_X4(A[0], A[1], A[2], A[3], aaddr);
#pragma unroll
            for (int ntp = 0; ntp < 8; ntp++) {
                uint32_t b0, b1, b2, b3;
                uint32_t baddr = sV + (uint32_t)((wn * 32 + ks2 * 16 + lrow + ((grp & 1) << 3)) * SV_STR
                                                 + (ntp * 16 + ((grp >> 1) << 3)) * 2);
                LDSM_X4_T(b0, b1, b2, b3, baddr);
                MMA_F16(Oc[2 * ntp],     A, b0, b1);
                MMA_F16(Oc[2 * ntp + 1], A, b2, b3);
            }
        }

        __syncthreads();
        if (kt < qi) load_v((kt + 1) * 64);
    }

    // ---- merge t-halves ----
    __syncthreads();
    if (wn == 1) {
#pragma unroll
        for (int nt = 0; nt < 16; nt++) {
            int col = nt * 8 + 2 * (lane & 3);
            *(float2*)&mergeO[ra * 128 + col]       = make_float2(Oc[nt][0], Oc[nt][1]);
            *(float2*)&mergeO[(ra + 8) * 128 + col] = make_float2(Oc[nt][2], Oc[nt][3]);
        }
        if ((lane & 3) == 0) {
            mergeM[ra] = m0;     mergeM[ra + 8] = m1;
            mergeL[ra] = l0;     mergeL[ra + 8] = l1;
        }
    }
    __syncthreads();
    if (wn == 0) {
        float M1a = mergeM[ra],     L1a = mergeL[ra];
        float M1b = mergeM[ra + 8], L1b = mergeL[ra + 8];
        float Ma = fmaxf(m0, M1a);
        float w0a = __expf(m0 - Ma), w1a = __expf(M1a - Ma);
        float inva = 1.0f / (l0 * w0a + L1a * w1a);
        float Mb = fmaxf(m1, M1b);
        float w0b = __expf(m1 - Mb), w1b = __expf(M1b - Mb);
        float invb = 1.0f / (l1 * w0b + L1b * w1b);

        size_t obase = ((size_t)(b * SEQ + q0)) * DIM + h * HD;
#pragma unroll
        for (int nt = 0; nt < 16; nt++) {
            int col = nt * 8 + 2 * (lane & 3);
            float2 o1a = *(float2*)&mergeO[ra * 128 + col];
            float2 o1b = *(float2*)&mergeO[(ra + 8) * 128 + col];
            float2 oa = make_float2((Oc[nt][0] * w0a + o1a.x * w1a) * inva,
                                    (Oc[nt][1] * w0a + o1a.y * w1a) * inva);
            float2 ob = make_float2((Oc[nt][2] * w0b + o1b.x * w1b) * invb,
                                    (Oc[nt][3] * w0b + o1b.y * w1b) * invb);
            *(float2*)&Oout[obase + (size_t)ra * DIM + col]       = oa;
            *(float2*)&Oout[obase + (size_t)(ra + 8) * DIM + col] = ob;
        }
    }
}

// ---------------------------------------------------------------------------
extern "C" void kernel_launch(void* const* d_in, const int* in_sizes, int n_in,
                              void* d_out, int out_size)
{
    const float* x  = (const float*)d_in[0];
    const float* wq = (const float*)d_in[1];
    const float* wk = (const float*)d_in[2];
    const float* wv = (const float*)d_in[3];
    const float* wo = (const float*)d_in[4];
    const float* fc = (const float*)d_in[5];
    const float* fs = (const float*)d_in[6];
    float* out = (float*)d_out;

    float *qp, *kp, *vp, *ap;
    __half *xs, *as, *wqs, *wks, *wvs, *wos, *qs2, *ks2, *vs2;
    cudaGetSymbolAddress((void**)&qp, g_q);
    cudaGetSymbolAddress((void**)&kp, g_k);
    cudaGetSymbolAddress((void**)&vp, g_v);
    cudaGetSymbolAddress((void**)&ap, g_attn);
    cudaGetSymbolAddress((void**)&xs, g_xs);
    cudaGetSymbolAddress((void**)&as, g_as);
    cudaGetSymbolAddress((void**)&wqs, g_wqs);
    cudaGetSymbolAddress((void**)&wks, g_wks);
    cudaGetSymbolAddress((void**)&wvs, g_wvs);
    cudaGetSymbolAddress((void**)&wos, g_wos);
    cudaGetSymbolAddress((void**)&qs2, g_qs2);
    cudaGetSymbolAddress((void**)&ks2, g_ks2);
    cudaGetSymbolAddress((void**)&vs2, g_vs2);

    cudaFuncSetAttribute(gemm_hmma, cudaFuncAttributeMaxDynamicSharedMemorySize, GSMEM);
    cudaFuncSetAttribute(attn_mma, cudaFuncAttributeMaxDynamicSharedMemorySize, ATT_SMEM);

    // fp16 conversions
    cvt_f16<<<(MROWS * KDIM / 8) / 256, 256>>>(x,  xs);
    cvt_f16<<<(DIM   * KDIM / 8) / 256, 256>>>(wq, wqs);
    cvt_f16<<<(KVDIM * KDIM / 8) / 256, 256>>>(wk, wks);
    cvt_f16<<<(KVDIM * KDIM / 8) / 256, 256>>>(wv, wvs);
    cvt_f16<<<(DIM   * KDIM / 8) / 256, 256>>>(wo, wos);

    // QKV projections (plain fp16 HMMA)
    gemm_hmma<<<dim3(DIM   / 128, MROWS / 128), 256, GSMEM>>>(xs, wqs, qp, MROWS, DIM);
    gemm_hmma<<<dim3(KVDIM / 128, MROWS / 128), 256, GSMEM>>>(xs, wks, kp, MROWS, KVDIM);
    gemm_hmma<<<dim3(KVDIM / 128, MROWS / 128), 256, GSMEM>>>(xs, wvs, vp, MROWS, KVDIM);

    // RoPE + fp16 pack
    rope_pack<1><<<(BATCH * NH  * SEQ * 16) / 256, 256>>>(qp, qs2, fc, fs);
    rope_pack<0><<<(BATCH * NKV * SEQ * 16) / 256, 256>>>(kp, ks2, fc, fs);
    cvt_v_f16<<<(BATCH * NKV * SEQ * 16) / 256, 256>>>(vp, vs2);

    // fp16 flash attention
    attn_mma<<<dim3(SEQ / 64, BATCH * NH), 256, ATT_SMEM>>>(qs2, ks2, vs2, ap);

    // Output projection
    cvt_f16<<<(MROWS * KDIM / 8) / 256, 256>>>(ap, as);
    gemm_hmma<<<dim3(DIM / 128, MROWS / 128), 256, GSMEM>>>(as, wos, out, MROWS, DIM);
}

// round 15
// speedup vs baseline: 2.7741x; 1.0181x over previous
#include <cuda_runtime.h>
#include <cuda_fp16.h>
#include <math.h>
#include <stdint.h>

#define BATCH 2
#define SEQ   2048
#define DIM   4096
#define NH    32
#define NKV   8
#define HD    128
#define MROWS 4096   // BATCH*SEQ
#define KVDIM 1024   // NKV*HD
#define KDIM  4096   // GEMM inner K

// ---------------- scratch (zero-init .bss, no runtime allocation) ----------
// plain fp16 GEMM operands
__device__ __half g_xs [(size_t)MROWS * KDIM];
__device__ __half g_as [(size_t)MROWS * KDIM];   // attn out, fp16, written by attn epilogue
__device__ __half g_wqs[(size_t)DIM   * KDIM];
__device__ __half g_wks[(size_t)KVDIM * KDIM];
__device__ __half g_wvs[(size_t)KVDIM * KDIM];
__device__ __half g_wos[(size_t)DIM   * KDIM];

// attention fp16 operands (written directly by QKV gemm epilogues)
__device__ __half g_qs2[(size_t)BATCH * NH  * SEQ * 256];  // Q (hi,lo) interleaved
__device__ __half g_ks2[(size_t)BATCH * NKV * SEQ * 256];  // K (k,k) dup
__device__ __half g_vs2[(size_t)BATCH * NKV * SEQ * HD];   // V plain

// ---------------- helpers ---------------------------------------------------
__device__ __forceinline__ uint32_t smem_u32(const void* p) {
    return (uint32_t)__cvta_generic_to_shared(p);
}
__device__ __forceinline__ void cp_async16(uint32_t dst, const void* src) {
    asm volatile("cp.async.cg.shared.global [%0], [%1], 16;" :: "r"(dst), "l"(src) : "memory");
}
__device__ __forceinline__ void cp_commit() {
    asm volatile("cp.async.commit_group;" ::: "memory");
}

#define LDSM_X4(r0, r1, r2, r3, addr) \
    asm volatile("ldmatrix.sync.aligned.m8n8.x4.shared.b16 {%0,%1,%2,%3}, [%4];" \
                 : "=r"(r0), "=r"(r1), "=r"(r2), "=r"(r3) : "r"(addr))

#define LDSM_X4_T(r0, r1, r2, r3, addr) \
    asm volatile("ldmatrix.sync.aligned.m8n8.x4.trans.shared.b16 {%0,%1,%2,%3}, [%4];" \
                 : "=r"(r0), "=r"(r1), "=r"(r2), "=r"(r3) : "r"(addr))

#define MMA_F16(d, a, b0v, b1v) \
    asm volatile("mma.sync.aligned.m16n8k16.row.col.f32.f16.f16.f32 " \
                 "{%0,%1,%2,%3}, {%4,%5,%6,%7}, {%8,%9}, {%0,%1,%2,%3};" \
                 : "+f"((d)[0]), "+f"((d)[1]), "+f"((d)[2]), "+f"((d)[3]) \
                 : "r"((a)[0]), "r"((a)[1]), "r"((a)[2]), "r"((a)[3]), \
                   "r"(b0v), "r"(b1v))

// ---------------------------------------------------------------------------
// fp32 -> fp16, coalesced (inputs/weights only)
// ---------------------------------------------------------------------------
__global__ void __launch_bounds__(256) cvt_f16(
    const float* __restrict__ src, __half* __restrict__ dst)
{
    size_t t = (size_t)blockIdx.x * 256 + threadIdx.x;
    float4 v0 = *(const float4*)&src[t * 8];
    float4 v1 = *(const float4*)&src[t * 8 + 4];
    float f[8] = {v0.x, v0.y, v0.z, v0.w, v1.x, v1.y, v1.z, v1.w};
    __align__(16) __half h[8];
#pragma unroll
    for (int j = 0; j < 8; j++) h[j] = __float2half_rn(f[j]);
    *(uint4*)&dst[t * 8] = *(uint4*)h;
}

// ---------------------------------------------------------------------------
// fp16 HMMA GEMM (R13 loop, proven). EPI: 0 = fp32 C store (final out);
// 1 = Q rope+scale -> g_qs2 (hi,lo); 2 = K rope -> g_ks2 (k,k); 3 = V -> g_vs2.
// ---------------------------------------------------------------------------
#define BKC         32
#define ROW_BYTES   80
#define STAGE_BYTES (256 * ROW_BYTES)
#define NSTAGE      4
#define GSMEM       (NSTAGE * STAGE_BYTES)
#define NITER       (KDIM / BKC)          // 128

template <int EPI>
__global__ void __launch_bounds__(256) gemm_hmma(
    const __half* __restrict__ A, const __half* __restrict__ Bm,
    float* __restrict__ C, const float* __restrict__ fc,
    const float* __restrict__ fs, int N)
{
    extern __shared__ __align__(1024) char smem[];
    const uint32_t sbase = smem_u32(smem);

    const int bm = blockIdx.y * 128;
    const int bn = blockIdx.x * 128;
    const int tid = threadIdx.x;
    const int wid = tid >> 5;
    const int lane = tid & 31;
    const int wm = wid & 3;
    const int wn = wid >> 2;

    const __half* ga0 = A  + (size_t)bm * KDIM;
    const __half* gb0 = Bm + (size_t)bn * KDIM;

    const int lc = tid & 3;
    const int lr = tid >> 2;

    auto load_stage = [&](int s, int chunk) {
        const uint32_t sa = sbase + (uint32_t)s * STAGE_BYTES;
        const size_t koff = (size_t)chunk * BKC + lc * 8;
#pragma unroll
        for (int j = 0; j < 4; j++) {
            int r = lr + j * 64;
            const __half* src = (r < 128)
                ? ga0 + (size_t)r * KDIM + koff
                : gb0 + (size_t)(r - 128) * KDIM + koff;
            cp_async16(sa + (uint32_t)(r * ROW_BYTES + lc * 16), src);
        }
        cp_commit();
    };

    float d[2][8][4];
#pragma unroll
    for (int mi = 0; mi < 2; mi++)
#pragma unroll
        for (int nj = 0; nj < 8; nj++)
#pragma unroll
            for (int q = 0; q < 4; q++) d[mi][nj][q] = 0.0f;

    const int grp  = lane >> 3;
    const int lrow = lane & 7;
    const int a_r = lrow + ((grp & 1) << 3);
    const int a_c = (grp >> 1) << 3;
    const int b_r = lrow + ((grp >> 1) << 3);
    const int b_c = (grp & 1) << 3;

    load_stage(0, 0);
    load_stage(1, 1);
    load_stage(2, 2);

    for (int i = 0; i < NITER; i++) {
        const int s = i & (NSTAGE - 1);
        asm volatile("cp.async.wait_group %0;" :: "n"(NSTAGE - 2) : "memory");
        __syncthreads();
        if (i + 3 < NITER) load_stage((i + 3) & (NSTAGE - 1), i + 3);
        else cp_commit();

        const uint32_t aB = sbase + (uint32_t)s * STAGE_BYTES;
        const uint32_t bB = aB + 128 * ROW_BYTES;
#pragma unroll
        for (int step = 0; step < 2; step++) {
            uint32_t af[2][4];
#pragma unroll
            for (int mi = 0; mi < 2; mi++) {
                uint32_t addr = aB + (uint32_t)((wm * 32 + mi * 16 + a_r) * ROW_BYTES
                                                + (step * 16 + a_c) * 2);
                LDSM_X4(af[mi][0], af[mi][1], af[mi][2], af[mi][3], addr);
            }
#pragma unroll
            for (int njp = 0; njp < 4; njp++) {
                uint32_t b0, b1, b2, b3;
                uint32_t addr = bB + (uint32_t)((wn * 64 + njp * 16 + b_r) * ROW_BYTES
                                                + (step * 16 + b_c) * 2);
                LDSM_X4(b0, b1, b2, b3, addr);
#pragma unroll
                for (int mi = 0; mi < 2; mi++) {
                    MMA_F16(d[mi][2 * njp],     af[mi], b0, b1);
                    MMA_F16(d[mi][2 * njp + 1], af[mi], b2, b3);
                }
            }
        }
    }

    // ------------------- epilogue -------------------
    const int er = lane >> 2;
    const int ec = (lane & 3) * 2;
#pragma unroll
    for (int mi = 0; mi < 2; mi++) {
#pragma unroll
        for (int nj = 0; nj < 8; nj++) {
            const int r0 = bm + wm * 32 + mi * 16 + er;   // global row (m)
            const int c0 = bn + wn * 64 + nj * 8 + ec;    // global col (even)

            if (EPI == 0) {
                *(float2*)&C[(size_t)r0 * N + c0]       = make_float2(d[mi][nj][0], d[mi][nj][1]);
                *(float2*)&C[(size_t)(r0 + 8) * N + c0] = make_float2(d[mi][nj][2], d[mi][nj][3]);
            } else if (EPI == 3) {
                const int kv = c0 >> 7, dl = c0 & 127;
#pragma unroll
                for (int half = 0; half < 2; half++) {
                    int m = r0 + half * 8;
                    int b = m >> 11, t = m & (SEQ - 1);
                    __half2 hv = __floats2half2_rn(d[mi][nj][2 * half], d[mi][nj][2 * half + 1]);
                    *(__half2*)&g_vs2[((size_t)(b * NKV + kv) * SEQ + t) * HD + dl] = hv;
                }
            } else {
                // Q (EPI==1) / K (EPI==2): rope applied to the (c0, c0+1) pair
                const int h = c0 >> 7, dl = c0 & 127;
                const int ip = dl >> 1;
#pragma unroll
                for (int half = 0; half < 2; half++) {
                    int m = r0 + half * 8;
                    int b = m >> 11, s = m & (SEQ - 1);
                    float cv = fc[s * 64 + ip];
                    float sv = fs[s * 64 + ip];
                    float xr = d[mi][nj][2 * half], xi = d[mi][nj][2 * half + 1];
                    float rr = xr * cv - xi * sv;
                    float ri = xr * sv + xi * cv;
                    if (EPI == 1) { rr *= 0.08838834764831845f; ri *= 0.08838834764831845f; }
                    __align__(8) __half o[4];
                    if (EPI == 1) {
                        __half hr = __float2half_rn(rr);
                        __half hi = __float2half_rn(ri);
                        o[0] = hr; o[1] = __float2half_rn(rr - __half2float(hr));
                        o[2] = hi; o[3] = __float2half_rn(ri - __half2float(hi));
                    } else {
                        __half hr = __float2half_rn(rr);
                        __half hi = __float2half_rn(ri);
                        o[0] = hr; o[1] = hr; o[2] = hi; o[3] = hi;
                    }
                    size_t rowo = (EPI == 1)
                        ? ((size_t)(b * NH  + h) * SEQ + s)
                        : ((size_t)(b * NKV + h) * SEQ + s);
                    __half* dp = (EPI == 1 ? g_qs2 : g_ks2) + rowo * 256 + dl * 2;
                    *(uint2*)dp = *(uint2*)o;
                }
            }
        }
    }
}

// ---------------------------------------------------------------------------
// fp16 causal flash attention (R13 core, proven); epilogue writes fp16 g_as.
// ---------------------------------------------------------------------------
#define SQ_STR   528
#define SK_STR   528
#define SV_STR   272
#define SP_STR   144
#define SQ_OFF   0
#define SK_OFF   33792
#define SV_OFF   67584
#define SP_OFF   84992
#define ATT_SMEM 94208

__global__ void __launch_bounds__(256) attn_mma(
    const __half* __restrict__ Qs, const __half* __restrict__ Ks,
    const __half* __restrict__ Vs, __half* __restrict__ Oas)
{
    extern __shared__ __align__(1024) char smem[];
    const uint32_t sQ = smem_u32(smem) + SQ_OFF;
    const uint32_t sK = smem_u32(smem) + SK_OFF;
    const uint32_t sV = smem_u32(smem) + SV_OFF;
    const uint32_t sP = smem_u32(smem) + SP_OFF;
    float* mergeO = (float*)smem;
    float* mergeM = (float*)(smem + 32768);
    float* mergeL = (float*)(smem + 32768 + 256);

    const int qi = (SEQ / 64 - 1) - blockIdx.x;
    const int bh = blockIdx.y;
    const int b = bh >> 5, h = bh & 31, kvh = h >> 2;
    const int q0 = qi * 64;
    const int tid = threadIdx.x;
    const int wid = tid >> 5, lane = tid & 31;
    const int wm = wid & 3, wn = wid >> 2;
    const int grp = lane >> 3, lrow = lane & 7;

    const __half* gk = Ks + ((size_t)(b * NKV + kvh) * SEQ) * 256;
    const __half* gv = Vs + ((size_t)(b * NKV + kvh) * SEQ) * HD;

    auto load_k = [&](int t0) {
#pragma unroll
        for (int j = 0; j < 8; j++) {
            int id = tid + j * 256;
            int r = id >> 5, c = id & 31;
            cp_async16(sK + (uint32_t)(r * SK_STR + c * 16),
                       gk + ((size_t)(t0 + r)) * 256 + c * 8);
        }
        cp_commit();
    };
    auto load_v = [&](int t0) {
#pragma unroll
        for (int j = 0; j < 4; j++) {
            int id = tid + j * 256;
            int r = id >> 4, c = id & 15;
            cp_async16(sV + (uint32_t)(r * SV_STR + c * 16),
                       gv + ((size_t)(t0 + r)) * HD + c * 8);
        }
        cp_commit();
    };

    const __half* gq = Qs + ((size_t)(b * NH + h) * SEQ + q0) * 256;
#pragma unroll
    for (int j = 0; j < 8; j++) {
        int id = tid + j * 256;
        int r = id >> 5, c = id & 31;
        cp_async16(sQ + (uint32_t)(r * SQ_STR + c * 16), gq + (size_t)r * 256 + c * 8);
    }
    cp_commit();
    load_k(0);
    load_v(0);

    float m0 = -1e30f, m1 = -1e30f, l0 = 0.0f, l1 = 0.0f;
    float Oc[16][4];
#pragma unroll
    for (int j = 0; j < 16; j++)
#pragma unroll
        for (int q = 0; q < 4; q++) Oc[j][q] = 0.0f;

    const int ra = wm * 16 + (lane >> 2);

    for (int kt = 0; kt <= qi; kt++) {
        asm volatile("cp.async.wait_group 0;" ::: "memory");
        __syncthreads();

        float Sa[4][4];
#pragma unroll
        for (int nt = 0; nt < 4; nt++)
#pragma unroll
            for (int q = 0; q < 4; q++) Sa[nt][q] = 0.0f;

#pragma unroll
        for (int ks = 0; ks < 16; ks++) {
            uint32_t A[4];
            uint32_t aaddr = sQ + (uint32_t)((wm * 16 + lrow + ((grp & 1) << 3)) * SQ_STR
                                             + (ks * 16 + ((grp >> 1) << 3)) * 2);
            LDSM_X4(A[0], A[1], A[2], A[3], aaddr);
#pragma unroll
            for (int ntp = 0; ntp < 2; ntp++) {
                uint32_t b0, b1, b2, b3;
                uint32_t baddr = sK + (uint32_t)((wn * 32 + ntp * 16 + lrow + ((grp >> 1) << 3)) * SK_STR
                                                 + (ks * 16 + ((grp & 1) << 3)) * 2);
                LDSM_X4(b0, b1, b2, b3, baddr);
                MMA_F16(Sa[2 * ntp],     A, b0, b1);
                MMA_F16(Sa[2 * ntp + 1], A, b2, b3);
            }
        }

        __syncthreads();
        if (kt < qi) load_k((kt + 1) * 64);

        if (kt == qi) {
#pragma unroll
            for (int nt = 0; nt < 4; nt++) {
                int tb = wn * 32 + nt * 8 + 2 * (lane & 3);
                if (tb     > ra)     Sa[nt][0] = -1e30f;
                if (tb + 1 > ra)     Sa[nt][1] = -1e30f;
                if (tb     > ra + 8) Sa[nt][2] = -1e30f;
                if (tb + 1 > ra + 8) Sa[nt][3] = -1e30f;
            }
        }

        float hm0 = -1e30f, hm1 = -1e30f;
#pragma unroll
        for (int nt = 0; nt < 4; nt++) {
            hm0 = fmaxf(hm0, fmaxf(Sa[nt][0], Sa[nt][1]));
            hm1 = fmaxf(hm1, fmaxf(Sa[nt][2], Sa[nt][3]));
        }
        hm0 = fmaxf(hm0, __shfl_xor_sync(0xffffffffu, hm0, 1));
        hm0 = fmaxf(hm0, __shfl_xor_sync(0xffffffffu, hm0, 2));
        hm1 = fmaxf(hm1, __shfl_xor_sync(0xffffffffu, hm1, 1));
        hm1 = fmaxf(hm1, __shfl_xor_sync(0xffffffffu, hm1, 2));

        float mn0 = fmaxf(m0, hm0), mn1 = fmaxf(m1, hm1);
        float al0 = __expf(m0 - mn0), al1 = __expf(m1 - mn1);
        m0 = mn0; m1 = mn1;

        float hs0 = 0.0f, hs1 = 0.0f;
#pragma unroll
        for (int nt = 0; nt < 4; nt++) {
            Sa[nt][0] = __expf(Sa[nt][0] - mn0); hs0 += Sa[nt][0];
            Sa[nt][1] = __expf(Sa[nt][1] - mn0); hs0 += Sa[nt][1];
            Sa[nt][2] = __expf(Sa[nt][2] - mn1); hs1 += Sa[nt][2];
            Sa[nt][3] = __expf(Sa[nt][3] - mn1); hs1 += Sa[nt][3];
        }
        hs0 += __shfl_xor_sync(0xffffffffu, hs0, 1);
        hs0 += __shfl_xor_sync(0xffffffffu, hs0, 2);
        hs1 += __shfl_xor_sync(0xffffffffu, hs1, 1);
        hs1 += __shfl_xor_sync(0xffffffffu, hs1, 2);
        l0 = l0 * al0 + hs0;
        l1 = l1 * al1 + hs1;
#pragma unroll
        for (int j = 0; j < 16; j++) {
            Oc[j][0] *= al0; Oc[j][1] *= al0;
            Oc[j][2] *= al1; Oc[j][3] *= al1;
        }

        __syncwarp();
#pragma unroll
        for (int nt = 0; nt < 4; nt++) {
            int tl0 = wn * 32 + nt * 8 + 2 * (lane & 3);
#pragma unroll
            for (int q = 0; q < 4; q++) {
                int row = ra + ((q >> 1) << 3);
                int t = tl0 + (q & 1);
                uint16_t pv = __half_as_ushort(__float2half_rn(Sa[nt][q]));
                uint32_t ad = sP + (uint32_t)(row * SP_STR + t * 2);
                asm volatile("st.shared.u16 [%0], %1;" :: "r"(ad), "h"(pv));
            }
        }
        __syncwarp();

#pragma unroll
        for (int ks2 = 0; ks2 < 2; ks2++) {
            uint32_t A[4];
            uint32_t aaddr = sP + (uint32_t)((wm * 16 + lrow + ((grp & 1) << 3)) * SP_STR
                                             + (wn * 32 + ks2 * 16 + ((grp >> 1) << 3)) * 2);
            LDSM_X4(A[0], A[1], A[2], A[3], aaddr);
#pragma unroll
            for (int ntp = 0; ntp < 8; ntp++) {
                uint32_t b0, b1, b2, b3;
                uint32_t baddr = sV + (uint32_t)((wn * 32 + ks2 * 16 + lrow + ((grp & 1) << 3)) * SV_STR
                                                 + (ntp * 16 + ((grp >> 1) << 3)) * 2);
                LDSM_X4_T(b0, b1, b2, b3, baddr);
                MMA_F16(Oc[2 * ntp],     A, b0, b1);
                MMA_F16(Oc[2 * ntp + 1], A, b2, b3);
            }
        }

        __syncthreads();
        if (kt < qi) load_v((kt + 1) * 64);
    }

    // ---- merge t-halves, write fp16 g_as ----
    __syncthreads();
    if (wn == 1) {
#pragma unroll
        for (int nt = 0; nt < 16; nt++) {
            int col = nt * 8 + 2 * (lane & 3);
            *(float2*)&mergeO[ra * 128 + col]       = make_float2(Oc[nt][0], Oc[nt][1]);
            *(float2*)&mergeO[(ra + 8) * 128 + col] = make_float2(Oc[nt][2], Oc[nt][3]);
        }
        if ((lane & 3) == 0) {
            mergeM[ra] = m0;     mergeM[ra + 8] = m1;
            mergeL[ra] = l0;     mergeL[ra + 8] = l1;
        }
    }
    __syncthreads();
    if (wn == 0) {
        float M1a = mergeM[ra],     L1a = mergeL[ra];
        float M1b = mergeM[ra + 8], L1b = mergeL[ra + 8];
        float Ma = fmaxf(m0, M1a);
        float w0a = __expf(m0 - Ma), w1a = __expf(M1a - Ma);
        float inva = 1.0f / (l0 * w0a + L1a * w1a);
        float Mb = fmaxf(m1, M1b);
        float w0b = __expf(m1 - Mb), w1b = __expf(M1b - Mb);
        float invb = 1.0f / (l1 * w0b + L1b * w1b);

        const size_t r0g = (size_t)(b * SEQ + q0 + ra);
#pragma unroll
        for (int nt = 0; nt < 16; nt++) {
            int col = nt * 8 + 2 * (lane & 3);
            float2 o1a = *(float2*)&mergeO[ra * 128 + col];
            float2 o1b = *(float2*)&mergeO[(ra + 8) * 128 + col];
            float oa0 = (Oc[nt][0] * w0a + o1a.x * w1a) * inva;
            float oa1 = (Oc[nt][1] * w0a + o1a.y * w1a) * inva;
            float ob0 = (Oc[nt][2] * w0b + o1b.x * w1b) * invb;
            float ob1 = (Oc[nt][3] * w0b + o1b.y * w1b) * invb;
            int cg = h * HD + col;
            *(__half2*)&Oas[r0g * DIM + cg]       = __floats2half2_rn(oa0, oa1);
            *(__half2*)&Oas[(r0g + 8) * DIM + cg] = __floats2half2_rn(ob0, ob1);
        }
    }
}

// ---------------------------------------------------------------------------
extern "C" void kernel_launch(void* const* d_in, const int* in_sizes, int n_in,
                              void* d_out, int out_size)
{
    const float* x  = (const float*)d_in[0];
    const float* wq = (const float*)d_in[1];
    const float* wk = (const float*)d_in[2];
    const float* wv = (const float*)d_in[3];
    const float* wo = (const float*)d_in[4];
    const float* fc = (const float*)d_in[5];
    const float* fs = (const float*)d_in[6];
    float* out = (float*)d_out;

    __half *xs, *as, *wqs, *wks, *wvs, *wos, *qs2, *ks2, *vs2;
    cudaGetSymbolAddress((void**)&xs, g_xs);
    cudaGetSymbolAddress((void**)&as, g_as);
    cudaGetSymbolAddress((void**)&wqs, g_wqs);
    cudaGetSymbolAddress((void**)&wks, g_wks);
    cudaGetSymbolAddress((void**)&wvs, g_wvs);
    cudaGetSymbolAddress((void**)&wos, g_wos);
    cudaGetSymbolAddress((void**)&qs2, g_qs2);
    cudaGetSymbolAddress((void**)&ks2, g_ks2);
    cudaGetSymbolAddress((void**)&vs2, g_vs2);

    cudaFuncSetAttribute(gemm_hmma<0>, cudaFuncAttributeMaxDynamicSharedMemorySize, GSMEM);
    cudaFuncSetAttribute(gemm_hmma<1>, cudaFuncAttributeMaxDynamicSharedMemorySize, GSMEM);
    cudaFuncSetAttribute(gemm_hmma<2>, cudaFuncAttributeMaxDynamicSharedMemorySize, GSMEM);
    cudaFuncSetAttribute(gemm_hmma<3>, cudaFuncAttributeMaxDynamicSharedMemorySize, GSMEM);
    cudaFuncSetAttribute(attn_mma, cudaFuncAttributeMaxDynamicSharedMemorySize, ATT_SMEM);

    // fp16 conversions (inputs/weights only)
    cvt_f16<<<(MROWS * KDIM / 8) / 256, 256>>>(x,  xs);
    cvt_f16<<<(DIM   * KDIM / 8) / 256, 256>>>(wq, wqs);
    cvt_f16<<<(KVDIM * KDIM / 8) / 256, 256>>>(wk, wks);
    cvt_f16<<<(KVDIM * KDIM / 8) / 256, 256>>>(wv, wvs);
    cvt_f16<<<(DIM   * KDIM / 8) / 256, 256>>>(wo, wos);

    // QKV projections with fused rope/pack epilogues
    gemm_hmma<1><<<dim3(DIM   / 128, MROWS / 128), 256, GSMEM>>>(xs, wqs, nullptr, fc, fs, DIM);
    gemm_hmma<2><<<dim3(KVDIM / 128, MROWS / 128), 256, GSMEM>>>(xs, wks, nullptr, fc, fs, KVDIM);
    gemm_hmma<3><<<dim3(KVDIM / 128, MROWS / 128), 256, GSMEM>>>(xs, wvs, nullptr, fc, fs, KVDIM);

    // fp16 flash attention (epilogue writes fp16 g_as)
    attn_mma<<<dim3(SEQ / 64, BATCH * NH), 256, ATT_SMEM>>>(qs2, ks2, vs2, as);

    // Output projection (fp32 epilogue)
    gemm_hmma<0><<<dim3(DIM / 128, MROWS / 128), 256, GSMEM>>>(as, wos, out, fc, fs, DIM);
}